// round 3
// baseline (speedup 1.0000x reference)
#include <cuda_runtime.h>

// ---------------------------------------------------------------------------
// GCN forward on GB300.
// Pipeline:
//   probe dtype -> zero scratch -> count deg -> dis=rsqrt(deg+1) ->
//   prefix-scan rowptr -> fill CSR(src,coef) -> W12 = lin1_w@conv1_w ->
//   GEMM1 t1 = x@W12+b12 -> gather conv1 (+bias,dropout,relu) -> h1 ->
//   GEMM2 t2 = h1@conv2_w -> gather conv2 (+bias) fused with mean-pool ->
//   final tiny GEMM -> out[128,10]
// ---------------------------------------------------------------------------

#define NN_CAP 100352          // >= 100000, padded
#define E_CAP  1600000
#define NGRAPH 128
#define HID    128
#define HID2   64
#define NCLS   10

__device__ int   g_is64;                 // 1 if edge_index/batch are int64
__device__ int   g_counts[NN_CAP];       // in-degree (w/o self loop)
__device__ int   g_rowptr[NN_CAP];
__device__ int   g_fill[NN_CAP];
__device__ int   g_chunkSum[256];
__device__ int   g_chunkOff[256];
__device__ float g_dis[NN_CAP];
__device__ int2  g_ecsr[E_CAP];          // {src, coef-as-bits} sorted by dst
__device__ float g_W12[128*128];
__device__ float g_b12[128];
__device__ float g_t1[100000*128];
__device__ float g_h1[100000*128];
__device__ float g_t2[100000*64];
__device__ float g_pooled[NGRAPH*HID2];
__device__ float g_gcnt[NGRAPH];

// ---- index loading (int64 vs int32 decided at runtime) --------------------
__device__ __forceinline__ int ld_idx(const void* p, long long i) {
    if (g_is64) return (int)((const long long*)p)[i];
    return ((const int*)p)[i];
}

// JAX may silently downgrade int64->int32. Detect: int32 pairs read as int64
// produce values >= 2^32 whenever the high partner word is nonzero.
__global__ void probe_dtype(const long long* ei) {
    if (blockIdx.x == 0 && threadIdx.x == 0) {
        int ok64 = 1;
        for (int i = 0; i < 128; i++) {
            long long v = ei[i];
            if (v < 0 || v >= 200000) { ok64 = 0; break; }
        }
        g_is64 = ok64;
    }
}

__global__ void zero_buffers(int Nn) {
    int i = blockIdx.x * blockDim.x + threadIdx.x;
    if (i < Nn) { g_counts[i] = 0; g_fill[i] = 0; }
    if (i < NGRAPH * HID2) g_pooled[i] = 0.0f;
    if (i < NGRAPH) g_gcnt[i] = 0.0f;
}

__global__ void count_dst(const void* ei, int E) {
    for (int i = blockIdx.x * blockDim.x + threadIdx.x; i < E;
         i += gridDim.x * blockDim.x) {
        int dst = ld_idx(ei, (long long)E + i);
        atomicAdd(&g_counts[dst], 1);
    }
}

__global__ void compute_dis(int Nn) {
    int i = blockIdx.x * blockDim.x + threadIdx.x;
    if (i < Nn) g_dis[i] = rsqrtf((float)(g_counts[i] + 1));   // +1 self loop
}

// ---- prefix scan over counts: rowptr (exclusive) ---------------------------
__global__ void chunk_sums(int Nn) {
    __shared__ int sm[256];
    int b = blockIdx.x, t = threadIdx.x;
    int s = 0;
    #pragma unroll
    for (int j = 0; j < 4; j++) {
        int idx = b * 1024 + t + j * 256;
        if (idx < Nn) s += g_counts[idx];
    }
    sm[t] = s; __syncthreads();
    for (int o = 128; o > 0; o >>= 1) {
        if (t < o) sm[t] += sm[t + o];
        __syncthreads();
    }
    if (t == 0) g_chunkSum[b] = sm[0];
}

__global__ void scan_top(int nb) {
    if (threadIdx.x == 0) {
        int acc = 0;
        for (int i = 0; i < nb; i++) { g_chunkOff[i] = acc; acc += g_chunkSum[i]; }
    }
}

__global__ void scan_chunks(int Nn) {
    __shared__ int warpSums[8];
    int b = blockIdx.x, t = threadIdx.x;
    int lane = t & 31, wid = t >> 5;
    int base = b * 1024 + t * 4;
    int v[4];
    #pragma unroll
    for (int j = 0; j < 4; j++) {
        int idx = base + j;
        v[j] = (idx < Nn) ? g_counts[idx] : 0;
    }
    int s0 = v[0], s1 = s0 + v[1], s2 = s1 + v[2], s3 = s2 + v[3];
    int tot = s3;
    int xv = tot;
    #pragma unroll
    for (int o = 1; o < 32; o <<= 1) {
        int y = __shfl_up_sync(0xffffffffu, xv, o);
        if (lane >= o) xv += y;
    }
    if (lane == 31) warpSums[wid] = xv;
    __syncthreads();
    if (t == 0) {
        int acc = 0;
        for (int i = 0; i < 8; i++) { int tmp = warpSums[i]; warpSums[i] = acc; acc += tmp; }
    }
    __syncthreads();
    int off = g_chunkOff[b] + warpSums[wid] + (xv - tot);
    int pre[4] = {0, s0, s1, s2};
    #pragma unroll
    for (int j = 0; j < 4; j++) {
        int idx = base + j;
        if (idx < Nn) g_rowptr[idx] = off + pre[j];
    }
}

__global__ void fill_csr(const void* ei, int E) {
    for (int i = blockIdx.x * blockDim.x + threadIdx.x; i < E;
         i += gridDim.x * blockDim.x) {
        int src = ld_idx(ei, i);
        int dst = ld_idx(ei, (long long)E + i);
        float coef = g_dis[src] * g_dis[dst];
        int pos = g_rowptr[dst] + atomicAdd(&g_fill[dst], 1);
        g_ecsr[pos] = make_int2(src, __float_as_int(coef));
    }
}

// ---- fuse lin1 into conv1 weight: W12 = lin1_w @ conv1_w -------------------
__global__ void fuse_w(const float* __restrict__ lin1_w,
                       const float* __restrict__ lin1_b,
                       const float* __restrict__ conv1_w) {
    int i = blockIdx.x, j = threadIdx.x;
    float s = 0.0f;
    #pragma unroll 8
    for (int k = 0; k < 128; k++) s += lin1_w[i * 128 + k] * conv1_w[k * 128 + j];
    g_W12[i * 128 + j] = s;
    if (i == 0) {
        float sb = 0.0f;
        #pragma unroll 8
        for (int k = 0; k < 128; k++) sb += lin1_b[k] * conv1_w[k * 128 + j];
        g_b12[j] = sb;
    }
}

// ---- tiled fp32 GEMM, K=128 fixed: C[M,N] = A[M,128] @ W[128,N] (+bias) ----
template <int N>
__device__ __forceinline__ void gemm_body(const float* __restrict__ A,
                                          const float* __restrict__ W,
                                          const float* __restrict__ bias,
                                          float* __restrict__ C, int M) {
    constexpr int CPT = N / 16;           // cols per thread (8 or 4)
    __shared__ float Xs[64 * 132];        // 64 rows x 128 cols, padded stride
    __shared__ float Ws[16 * N];          // K-chunk of W
    int tx = threadIdx.x & 15, ty = threadIdx.x >> 4;
    int row0 = blockIdx.x * 64;

    const float4* A4 = (const float4*)A;
    for (int idx = threadIdx.x; idx < 2048; idx += 256) {
        int r = idx >> 5, c4 = idx & 31;
        float4 v = (row0 + r < M) ? A4[(size_t)(row0 + r) * 32 + c4]
                                  : make_float4(0.f, 0.f, 0.f, 0.f);
        *(float4*)&Xs[r * 132 + c4 * 4] = v;
    }

    float acc[4][CPT];
    #pragma unroll
    for (int r = 0; r < 4; r++)
        #pragma unroll
        for (int c = 0; c < CPT; c++) acc[r][c] = 0.0f;

    for (int kk = 0; kk < 128; kk += 16) {
        __syncthreads();
        const float4* W4 = (const float4*)W;
        for (int idx = threadIdx.x; idx < 16 * N / 4; idx += 256)
            ((float4*)Ws)[idx] = W4[(size_t)kk * (N / 4) + idx];
        __syncthreads();
        #pragma unroll
        for (int k = 0; k < 16; k++) {
            float a[4];
            #pragma unroll
            for (int r = 0; r < 4; r++) a[r] = Xs[(ty * 4 + r) * 132 + kk + k];
            #pragma unroll
            for (int c = 0; c < CPT; c++) {
                float w = Ws[k * N + tx * CPT + c];
                #pragma unroll
                for (int r = 0; r < 4; r++) acc[r][c] += a[r] * w;
            }
        }
    }

    #pragma unroll
    for (int r = 0; r < 4; r++) {
        int row = row0 + ty * 4 + r;
        if (row < M) {
            #pragma unroll
            for (int c = 0; c < CPT; c += 4) {
                int col = tx * CPT + c;
                float4 v;
                v.x = acc[r][c];     v.y = acc[r][c + 1];
                v.z = acc[r][c + 2]; v.w = acc[r][c + 3];
                if (bias) {
                    v.x += bias[col];     v.y += bias[col + 1];
                    v.z += bias[col + 2]; v.w += bias[col + 3];
                }
                *(float4*)&C[(size_t)row * N + col] = v;
            }
        }
    }
}

__global__ __launch_bounds__(256) void gemm1_kernel(const float* __restrict__ x, int M) {
    gemm_body<128>(x, g_W12, g_b12, g_t1, M);
}
__global__ __launch_bounds__(256) void gemm2_kernel(const float* __restrict__ W, int M) {
    gemm_body<64>(g_h1, W, nullptr, g_t2, M);
}

// ---- conv1 gather: warp per dst node, +bias, +self-loop, dropout, relu -----
__global__ void gather_conv1(const float* __restrict__ conv1_b,
                             const float* __restrict__ drop_u, int Nn) {
    int warp = (blockIdx.x * blockDim.x + threadIdx.x) >> 5;
    if (warp >= Nn) return;
    int lane = threadIdx.x & 31;
    int i = warp;
    const float4* tb = (const float4*)g_t1;

    float4 acc = ((const float4*)conv1_b)[lane];
    float d = g_dis[i];
    float dsq = d * d;
    float4 v = tb[(size_t)i * 32 + lane];
    acc.x += dsq * v.x; acc.y += dsq * v.y; acc.z += dsq * v.z; acc.w += dsq * v.w;

    int s = g_rowptr[i], e = s + g_counts[i];
    #pragma unroll 4
    for (int j = s; j < e; j++) {
        int2 ed = __ldg(&g_ecsr[j]);
        float c = __int_as_float(ed.y);
        float4 w = tb[(size_t)ed.x * 32 + lane];
        acc.x += c * w.x; acc.y += c * w.y; acc.z += c * w.z; acc.w += c * w.w;
    }

    float4 u = ((const float4*)drop_u)[(size_t)i * 32 + lane];
    float4 o;
    o.x = (u.x >= 0.5f) ? fmaxf(acc.x, 0.f) * 2.f : 0.f;
    o.y = (u.y >= 0.5f) ? fmaxf(acc.y, 0.f) * 2.f : 0.f;
    o.z = (u.z >= 0.5f) ? fmaxf(acc.z, 0.f) * 2.f : 0.f;
    o.w = (u.w >= 0.5f) ? fmaxf(acc.w, 0.f) * 2.f : 0.f;
    ((float4*)g_h1)[(size_t)i * 32 + lane] = o;
}

// ---- conv2 gather fused with graph mean-pool accumulation ------------------
__global__ void gather_conv2_pool(const float* __restrict__ conv2_b,
                                  const void* __restrict__ batch, int Nn) {
    int warp = (blockIdx.x * blockDim.x + threadIdx.x) >> 5;
    if (warp >= Nn) return;
    int lane = threadIdx.x & 31;
    int i = warp;
    const float2* tb = (const float2*)g_t2;

    float2 acc = ((const float2*)conv2_b)[lane];
    float d = g_dis[i];
    float dsq = d * d;
    float2 v = tb[(size_t)i * 32 + lane];
    acc.x += dsq * v.x; acc.y += dsq * v.y;

    int s = g_rowptr[i], e = s + g_counts[i];
    #pragma unroll 4
    for (int j = s; j < e; j++) {
        int2 ed = __ldg(&g_ecsr[j]);
        float c = __int_as_float(ed.y);
        float2 w = tb[(size_t)ed.x * 32 + lane];
        acc.x += c * w.x; acc.y += c * w.y;
    }

    int g = ld_idx(batch, i);
    atomicAdd(&g_pooled[g * HID2 + lane * 2], acc.x);
    atomicAdd(&g_pooled[g * HID2 + lane * 2 + 1], acc.y);
    if (lane == 0) atomicAdd(&g_gcnt[g], 1.0f);
}

// ---- final: out[g,c] = (pooled[g]/cnt[g]) @ lin2_w + lin2_b ----------------
__global__ void final_lin(const float* __restrict__ lin2_w,
                          const float* __restrict__ lin2_b,
                          float* __restrict__ out) {
    int g = blockIdx.x;
    int c = threadIdx.x;
    if (c >= NCLS) return;
    float inv = 1.0f / fmaxf(g_gcnt[g], 1.0f);
    float s = lin2_b[c];
    #pragma unroll
    for (int dd = 0; dd < HID2; dd++)
        s += g_pooled[g * HID2 + dd] * inv * lin2_w[dd * NCLS + c];
    out[g * NCLS + c] = s;
}

// ---------------------------------------------------------------------------
extern "C" void kernel_launch(void* const* d_in, const int* in_sizes, int n_in,
                              void* d_out, int out_size) {
    const float* x     = (const float*)d_in[0];
    const void*  ei    = d_in[1];
    const void*  batch = d_in[2];
    // num_graphs may appear as a size-1 scalar input at index 3
    int idx = 3;
    if (n_in >= 13 && in_sizes[3] == 1) idx = 4;
    const float* drop_u  = (const float*)d_in[idx++];
    const float* lin1_w  = (const float*)d_in[idx++];
    const float* lin1_b  = (const float*)d_in[idx++];
    const float* conv1_w = (const float*)d_in[idx++];
    const float* conv1_b = (const float*)d_in[idx++];
    const float* conv2_w = (const float*)d_in[idx++];
    const float* conv2_b = (const float*)d_in[idx++];
    const float* lin2_w  = (const float*)d_in[idx++];
    const float* lin2_b  = (const float*)d_in[idx++];
    float* out = (float*)d_out;

    int Nn = in_sizes[0] / 128;
    int E  = in_sizes[1] / 2;
    if (Nn > 100000) Nn = 100000;
    if (E > E_CAP) E = E_CAP;
    int nb = (Nn + 1023) / 1024;

    probe_dtype<<<1, 1>>>((const long long*)ei);
    zero_buffers<<<(Nn + 255) / 256, 256>>>(Nn);
    count_dst<<<2048, 256>>>(ei, E);
    compute_dis<<<(Nn + 255) / 256, 256>>>(Nn);
    chunk_sums<<<nb, 256>>>(Nn);
    scan_top<<<1, 1>>>(nb);
    scan_chunks<<<nb, 256>>>(Nn);
    fill_csr<<<2048, 256>>>(ei, E);
    fuse_w<<<128, 128>>>(lin1_w, lin1_b, conv1_w);
    gemm1_kernel<<<(Nn + 63) / 64, 256>>>(x, Nn);
    gather_conv1<<<(Nn * 32 + 255) / 256, 256>>>(conv1_b, drop_u, Nn);
    gemm2_kernel<<<(Nn + 63) / 64, 256>>>(conv2_w, Nn);
    gather_conv2_pool<<<(Nn * 32 + 255) / 256, 256>>>(conv2_b, batch, Nn);
    final_lin<<<NGRAPH, 32>>>(lin2_w, lin2_b, out);
}

// round 6
// speedup vs baseline: 1.1843x; 1.1843x over previous
#include <cuda_runtime.h>

// ---------------------------------------------------------------------------
// GCN forward on GB300.
//   zero -> fuse_w -> probe -> GEMM1(tf32-3x MMA) -> count -> dis -> scan ->
//   fill CSR -> gather conv1 (+bias,dropout,relu) -> GEMM2(tf32-3x) ->
//   gather conv2 + mean-pool -> final linear
// GEMMs run on tensor cores: mma.sync.m16n8k8 tf32 with 3-term error
// compensation (hi*hi + hi*lo + lo*hi) == fp32-grade accuracy.
// ---------------------------------------------------------------------------

#define NN_CAP 100352
#define E_CAP  1600000
#define NGRAPH 128
#define HID    128
#define HID2   64
#define NCLS   10

__device__ int   g_is64;
__device__ int   g_counts[NN_CAP];
__device__ int   g_rowptr[NN_CAP];
__device__ int   g_fill[NN_CAP];
__device__ int   g_chunkSum[256];
__device__ int   g_chunkOff[256];
__device__ float g_dis[NN_CAP];
__device__ int2  g_ecsr[E_CAP];
__device__ float g_W12[128*128];
__device__ float g_b12[128];
__device__ float g_t1[100000*128];
__device__ float g_h1[100000*128];
__device__ float g_t2[100000*64];
__device__ float g_pooled[NGRAPH*HID2];
__device__ float g_gcnt[NGRAPH];

// ---- index loading (int64 vs int32 decided at runtime) ---------------------
__device__ __forceinline__ int ld_idx(const void* p, long long i) {
    if (g_is64) return (int)((const long long*)p)[i];
    return ((const int*)p)[i];
}

__global__ void probe_dtype(const long long* ei) {
    if (blockIdx.x == 0 && threadIdx.x == 0) {
        int ok64 = 1;
        for (int i = 0; i < 128; i++) {
            long long v = ei[i];
            if (v < 0 || v >= 200000) { ok64 = 0; break; }
        }
        g_is64 = ok64;
    }
}

__global__ void zero_buffers(int Nn) {
    int i = blockIdx.x * blockDim.x + threadIdx.x;
    if (i < Nn) { g_counts[i] = 0; g_fill[i] = 0; }
    if (i < NGRAPH * HID2) g_pooled[i] = 0.0f;
    if (i < NGRAPH) g_gcnt[i] = 0.0f;
}

__global__ void count_dst(const void* ei, int E) {
    for (int i = blockIdx.x * blockDim.x + threadIdx.x; i < E;
         i += gridDim.x * blockDim.x) {
        int dst = ld_idx(ei, (long long)E + i);
        atomicAdd(&g_counts[dst], 1);
    }
}

__global__ void compute_dis(int Nn) {
    int i = blockIdx.x * blockDim.x + threadIdx.x;
    if (i < Nn) g_dis[i] = rsqrtf((float)(g_counts[i] + 1));
}

// ---- prefix scan -----------------------------------------------------------
__global__ void chunk_sums(int Nn) {
    __shared__ int sm[256];
    int b = blockIdx.x, t = threadIdx.x;
    int s = 0;
    #pragma unroll
    for (int j = 0; j < 4; j++) {
        int idx = b * 1024 + t + j * 256;
        if (idx < Nn) s += g_counts[idx];
    }
    sm[t] = s; __syncthreads();
    for (int o = 128; o > 0; o >>= 1) {
        if (t < o) sm[t] += sm[t + o];
        __syncthreads();
    }
    if (t == 0) g_chunkSum[b] = sm[0];
}

__global__ void scan_top(int nb) {
    if (threadIdx.x == 0) {
        int acc = 0;
        for (int i = 0; i < nb; i++) { g_chunkOff[i] = acc; acc += g_chunkSum[i]; }
    }
}

__global__ void scan_chunks(int Nn) {
    __shared__ int warpSums[8];
    int b = blockIdx.x, t = threadIdx.x;
    int lane = t & 31, wid = t >> 5;
    int base = b * 1024 + t * 4;
    int v[4];
    #pragma unroll
    for (int j = 0; j < 4; j++) {
        int idx = base + j;
        v[j] = (idx < Nn) ? g_counts[idx] : 0;
    }
    int s0 = v[0], s1 = s0 + v[1], s2 = s1 + v[2], s3 = s2 + v[3];
    int tot = s3;
    int xv = tot;
    #pragma unroll
    for (int o = 1; o < 32; o <<= 1) {
        int y = __shfl_up_sync(0xffffffffu, xv, o);
        if (lane >= o) xv += y;
    }
    if (lane == 31) warpSums[wid] = xv;
    __syncthreads();
    if (t == 0) {
        int acc = 0;
        for (int i = 0; i < 8; i++) { int tmp = warpSums[i]; warpSums[i] = acc; acc += tmp; }
    }
    __syncthreads();
    int off = g_chunkOff[b] + warpSums[wid] + (xv - tot);
    int pre[4] = {0, s0, s1, s2};
    #pragma unroll
    for (int j = 0; j < 4; j++) {
        int idx = base + j;
        if (idx < Nn) g_rowptr[idx] = off + pre[j];
    }
}

__global__ void fill_csr(const void* ei, int E) {
    for (int i = blockIdx.x * blockDim.x + threadIdx.x; i < E;
         i += gridDim.x * blockDim.x) {
        int src = ld_idx(ei, i);
        int dst = ld_idx(ei, (long long)E + i);
        float coef = g_dis[src] * g_dis[dst];
        int pos = g_rowptr[dst] + atomicAdd(&g_fill[dst], 1);
        g_ecsr[pos] = make_int2(src, __float_as_int(coef));
    }
}

// ---- fuse lin1 into conv1 weight -------------------------------------------
__global__ void fuse_w(const float* __restrict__ lin1_w,
                       const float* __restrict__ lin1_b,
                       const float* __restrict__ conv1_w) {
    int i = blockIdx.x, j = threadIdx.x;
    float s = 0.0f;
    #pragma unroll 8
    for (int k = 0; k < 128; k++) s += lin1_w[i * 128 + k] * conv1_w[k * 128 + j];
    g_W12[i * 128 + j] = s;
    if (i == 0) {
        float sb = 0.0f;
        #pragma unroll 8
        for (int k = 0; k < 128; k++) sb += lin1_b[k] * conv1_w[k * 128 + j];
        g_b12[j] = sb;
    }
}

// ---- TF32 tensor-core GEMM with 3-term compensation ------------------------
__device__ __forceinline__ void tf32_split(float v, unsigned& hi, unsigned& lo) {
    asm("cvt.rna.tf32.f32 %0, %1;" : "=r"(hi) : "f"(v));
    float r = v - __uint_as_float(hi);
    asm("cvt.rna.tf32.f32 %0, %1;" : "=r"(lo) : "f"(r));
}

__device__ __forceinline__ void mma8(float* d, const unsigned* a, const unsigned* b) {
    asm volatile(
        "mma.sync.aligned.m16n8k8.row.col.f32.tf32.tf32.f32 "
        "{%0,%1,%2,%3}, {%4,%5,%6,%7}, {%8,%9}, {%0,%1,%2,%3};"
        : "+f"(d[0]), "+f"(d[1]), "+f"(d[2]), "+f"(d[3])
        : "r"(a[0]), "r"(a[1]), "r"(a[2]), "r"(a[3]), "r"(b[0]), "r"(b[1]));
}

// C[M,BN] = A[M,128] @ B[128,BN] (+ g_b12 if HB). 128-row block, 256 threads.
template <int BN, bool HB>
__device__ __forceinline__ void gemm_tf32_body(const float* __restrict__ Ag,
                                               const float* __restrict__ Bg,
                                               float* __restrict__ Cg, int M) {
    constexpr int WN = (BN == 128) ? 4 : 2;     // warps along N
    constexpr int WM = 8 / WN;                  // warps along M
    constexpr int MI = (128 / WM) / 16;         // m16 frags per warp (4 / 2)
    constexpr int NI = 4;                       // n8 frags (warp N-tile = 32)
    constexpr int SA = 20;                      // A smem stride (conflict-free)
    constexpr int SB = BN + 8;                  // B smem stride (conflict-free)

    __shared__ unsigned sAhi[128 * SA], sAlo[128 * SA];
    __shared__ unsigned sBhi[16 * SB],  sBlo[16 * SB];

    int tid = threadIdx.x, lane = tid & 31, wid = tid >> 5;
    int wm = wid % WM, wn = wid / WM;
    int row0 = blockIdx.x * 128;

    float acc[MI][NI][4];
    #pragma unroll
    for (int mi = 0; mi < MI; mi++)
        #pragma unroll
        for (int ni = 0; ni < NI; ni++)
            #pragma unroll
            for (int r = 0; r < 4; r++) acc[mi][ni][r] = 0.0f;

    for (int kk = 0; kk < 128; kk += 16) {
        __syncthreads();
        // A chunk: 128 rows x 16 cols (fp32 -> hi/lo tf32)
        #pragma unroll
        for (int f = tid; f < 512; f += 256) {
            int r = f >> 2, c4 = f & 3;
            float4 v = make_float4(0.f, 0.f, 0.f, 0.f);
            if (row0 + r < M)
                v = ((const float4*)Ag)[(size_t)(row0 + r) * 32 + (kk >> 2) + c4];
            uint4 h, l;
            tf32_split(v.x, h.x, l.x); tf32_split(v.y, h.y, l.y);
            tf32_split(v.z, h.z, l.z); tf32_split(v.w, h.w, l.w);
            *(uint4*)&sAhi[r * SA + c4 * 4] = h;
            *(uint4*)&sAlo[r * SA + c4 * 4] = l;
        }
        // B chunk: 16 rows x BN cols
        #pragma unroll
        for (int f = tid; f < 16 * BN / 4; f += 256) {
            int r = f / (BN / 4), c4 = f % (BN / 4);
            float4 v = ((const float4*)Bg)[(size_t)(kk + r) * (BN / 4) + c4];
            uint4 h, l;
            tf32_split(v.x, h.x, l.x); tf32_split(v.y, h.y, l.y);
            tf32_split(v.z, h.z, l.z); tf32_split(v.w, h.w, l.w);
            *(uint4*)&sBhi[r * SB + c4 * 4] = h;
            *(uint4*)&sBlo[r * SB + c4 * 4] = l;
        }
        __syncthreads();

        #pragma unroll
        for (int ks = 0; ks < 2; ks++) {
            int kb = ks * 8;
            unsigned ahi[MI][4], alo[MI][4];
            #pragma unroll
            for (int mi = 0; mi < MI; mi++) {
                int r = wm * (MI * 16) + mi * 16 + (lane >> 2);
                int c = kb + (lane & 3);
                ahi[mi][0] = sAhi[r * SA + c];
                ahi[mi][1] = sAhi[(r + 8) * SA + c];
                ahi[mi][2] = sAhi[r * SA + c + 4];
                ahi[mi][3] = sAhi[(r + 8) * SA + c + 4];
                alo[mi][0] = sAlo[r * SA + c];
                alo[mi][1] = sAlo[(r + 8) * SA + c];
                alo[mi][2] = sAlo[r * SA + c + 4];
                alo[mi][3] = sAlo[(r + 8) * SA + c + 4];
            }
            unsigned bhi[NI][2], blo[NI][2];
            #pragma unroll
            for (int ni = 0; ni < NI; ni++) {
                int c = wn * 32 + ni * 8 + (lane >> 2);
                int r = kb + (lane & 3);
                bhi[ni][0] = sBhi[r * SB + c];
                bhi[ni][1] = sBhi[(r + 4) * SB + c];
                blo[ni][0] = sBlo[r * SB + c];
                blo[ni][1] = sBlo[(r + 4) * SB + c];
            }
            #pragma unroll
            for (int mi = 0; mi < MI; mi++)
                #pragma unroll
                for (int ni = 0; ni < NI; ni++) mma8(acc[mi][ni], ahi[mi], bhi[ni]);
            #pragma unroll
            for (int mi = 0; mi < MI; mi++)
                #pragma unroll
                for (int ni = 0; ni < NI; ni++) mma8(acc[mi][ni], ahi[mi], blo[ni]);
            #pragma unroll
            for (int mi = 0; mi < MI; mi++)
                #pragma unroll
                for (int ni = 0; ni < NI; ni++) mma8(acc[mi][ni], alo[mi], bhi[ni]);
        }
    }

    // epilogue
    #pragma unroll
    for (int mi = 0; mi < MI; mi++) {
        int r = row0 + wm * (MI * 16) + mi * 16 + (lane >> 2);
        #pragma unroll
        for (int ni = 0; ni < NI; ni++) {
            int c = wn * 32 + ni * 8 + (lane & 3) * 2;
            float bx = 0.f, by = 0.f;
            if (HB) { bx = g_b12[c]; by = g_b12[c + 1]; }
            float2 v0 = make_float2(acc[mi][ni][0] + bx, acc[mi][ni][1] + by);
            float2 v1 = make_float2(acc[mi][ni][2] + bx, acc[mi][ni][3] + by);
            if (r < M)     *(float2*)&Cg[(size_t)r * BN + c] = v0;
            if (r + 8 < M) *(float2*)&Cg[(size_t)(r + 8) * BN + c] = v1;
        }
    }
}

__global__ __launch_bounds__(256) void gemm1_kernel(const float* __restrict__ x, int M) {
    gemm_tf32_body<128, true>(x, g_W12, g_t1, M);
}
__global__ __launch_bounds__(256) void gemm2_kernel(const float* __restrict__ W, int M) {
    gemm_tf32_body<64, false>(g_h1, W, g_t2, M);
}

// ---- conv1 gather ----------------------------------------------------------
__global__ void gather_conv1(const float* __restrict__ conv1_b,
                             const float* __restrict__ drop_u, int Nn) {
    int warp = (blockIdx.x * blockDim.x + threadIdx.x) >> 5;
    if (warp >= Nn) return;
    int lane = threadIdx.x & 31;
    int i = warp;
    const float4* tb = (const float4*)g_t1;

    float4 acc = ((const float4*)conv1_b)[lane];
    float d = g_dis[i];
    float dsq = d * d;
    float4 v = tb[(size_t)i * 32 + lane];
    acc.x += dsq * v.x; acc.y += dsq * v.y; acc.z += dsq * v.z; acc.w += dsq * v.w;

    int s = g_rowptr[i], e = s + g_counts[i];
    #pragma unroll 4
    for (int j = s; j < e; j++) {
        int2 ed = __ldg(&g_ecsr[j]);
        float c = __int_as_float(ed.y);
        float4 w = tb[(size_t)ed.x * 32 + lane];
        acc.x += c * w.x; acc.y += c * w.y; acc.z += c * w.z; acc.w += c * w.w;
    }

    float4 u = ((const float4*)drop_u)[(size_t)i * 32 + lane];
    float4 o;
    o.x = (u.x >= 0.5f) ? fmaxf(acc.x, 0.f) * 2.f : 0.f;
    o.y = (u.y >= 0.5f) ? fmaxf(acc.y, 0.f) * 2.f : 0.f;
    o.z = (u.z >= 0.5f) ? fmaxf(acc.z, 0.f) * 2.f : 0.f;
    o.w = (u.w >= 0.5f) ? fmaxf(acc.w, 0.f) * 2.f : 0.f;
    ((float4*)g_h1)[(size_t)i * 32 + lane] = o;
}

// ---- conv2 gather + mean-pool ----------------------------------------------
__global__ void gather_conv2_pool(const float* __restrict__ conv2_b,
                                  const void* __restrict__ batch, int Nn) {
    int warp = (blockIdx.x * blockDim.x + threadIdx.x) >> 5;
    if (warp >= Nn) return;
    int lane = threadIdx.x & 31;
    int i = warp;
    const float2* tb = (const float2*)g_t2;

    float2 acc = ((const float2*)conv2_b)[lane];
    float d = g_dis[i];
    float dsq = d * d;
    float2 v = tb[(size_t)i * 32 + lane];
    acc.x += dsq * v.x; acc.y += dsq * v.y;

    int s = g_rowptr[i], e = s + g_counts[i];
    #pragma unroll 4
    for (int j = s; j < e; j++) {
        int2 ed = __ldg(&g_ecsr[j]);
        float c = __int_as_float(ed.y);
        float2 w = tb[(size_t)ed.x * 32 + lane];
        acc.x += c * w.x; acc.y += c * w.y;
    }

    int g = ld_idx(batch, i);
    atomicAdd(&g_pooled[g * HID2 + lane * 2], acc.x);
    atomicAdd(&g_pooled[g * HID2 + lane * 2 + 1], acc.y);
    if (lane == 0) atomicAdd(&g_gcnt[g], 1.0f);
}

__global__ void final_lin(const float* __restrict__ lin2_w,
                          const float* __restrict__ lin2_b,
                          float* __restrict__ out) {
    int g = blockIdx.x;
    int c = threadIdx.x;
    if (c >= NCLS) return;
    float inv = 1.0f / fmaxf(g_gcnt[g], 1.0f);
    float s = lin2_b[c];
    #pragma unroll
    for (int dd = 0; dd < HID2; dd++)
        s += g_pooled[g * HID2 + dd] * inv * lin2_w[dd * NCLS + c];
    out[g * NCLS + c] = s;
}

// ---------------------------------------------------------------------------
extern "C" void kernel_launch(void* const* d_in, const int* in_sizes, int n_in,
                              void* d_out, int out_size) {
    const float* x     = (const float*)d_in[0];
    const void*  ei    = d_in[1];
    const void*  batch = d_in[2];
    int idx = 3;
    if (n_in >= 13 && in_sizes[3] == 1) idx = 4;
    const float* drop_u  = (const float*)d_in[idx++];
    const float* lin1_w  = (const float*)d_in[idx++];
    const float* lin1_b  = (const float*)d_in[idx++];
    const float* conv1_w = (const float*)d_in[idx++];
    const float* conv1_b = (const float*)d_in[idx++];
    const float* conv2_w = (const float*)d_in[idx++];
    const float* conv2_b = (const float*)d_in[idx++];
    const float* lin2_w  = (const float*)d_in[idx++];
    const float* lin2_b  = (const float*)d_in[idx++];
    float* out = (float*)d_out;

    int Nn = in_sizes[0] / 128;
    int E  = in_sizes[1] / 2;
    if (Nn > 100000) Nn = 100000;
    if (E > E_CAP) E = E_CAP;
    int nb = (Nn + 1023) / 1024;

    // Order chosen so gemm1 is the 4th launch -> it lands in the ncu window.
    zero_buffers<<<(Nn + 255) / 256, 256>>>(Nn);
    fuse_w<<<128, 128>>>(lin1_w, lin1_b, conv1_w);
    probe_dtype<<<1, 1>>>((const long long*)ei);
    gemm1_kernel<<<(Nn + 127) / 128, 256>>>(x, Nn);
    count_dst<<<2048, 256>>>(ei, E);
    compute_dis<<<(Nn + 255) / 256, 256>>>(Nn);
    chunk_sums<<<nb, 256>>>(Nn);
    scan_top<<<1, 1>>>(nb);
    scan_chunks<<<nb, 256>>>(Nn);
    fill_csr<<<2048, 256>>>(ei, E);
    gather_conv1<<<(Nn * 32 + 255) / 256, 256>>>(conv1_b, drop_u, Nn);
    gemm2_kernel<<<(Nn + 127) / 128, 256>>>(conv2_w, Nn);
    gather_conv2_pool<<<(Nn * 32 + 255) / 256, 256>>>(conv2_b, batch, Nn);
    final_lin<<<NGRAPH, 32>>>(lin2_w, lin2_b, out);
}

// round 8
// speedup vs baseline: 1.2477x; 1.0536x over previous
#include <cuda_runtime.h>

// ---------------------------------------------------------------------------
// GCN forward on GB300.  Round 7:
//  - B operands pre-split to tf32 hi/lo ONCE (fuse_w) instead of per-CTA
//  - count_dst grid-fused into the gemm1 launch (independent work overlaps)
//  - compute_dis fused into chunk_sums
// GEMMs: mma.sync.m16n8k8 tf32, 3-term compensation (fp32-grade accuracy).
// ---------------------------------------------------------------------------

#define NN_CAP 100352
#define E_CAP  1600000
#define NGRAPH 128
#define HID    128
#define HID2   64
#define NCLS   10

__device__ int      g_is64;
__device__ int      g_counts[NN_CAP];
__device__ int      g_rowptr[NN_CAP];
__device__ int      g_fill[NN_CAP];
__device__ int      g_chunkSum[256];
__device__ int      g_chunkOff[256];
__device__ float    g_dis[NN_CAP];
__device__ int2     g_ecsr[E_CAP];
__device__ unsigned g_W12hi[128*128], g_W12lo[128*128];   // pre-split B of GEMM1
__device__ unsigned g_W2hi[128*64],  g_W2lo[128*64];      // pre-split B of GEMM2
__device__ float    g_b12[128];
__device__ float    g_t1[100000*128];
__device__ float    g_h1[100000*128];
__device__ float    g_t2[100000*64];
__device__ float    g_pooled[NGRAPH*HID2];
__device__ float    g_gcnt[NGRAPH];

// ---- index loading (int64 vs int32 decided at runtime) ---------------------
__device__ __forceinline__ int ld_idx(const void* p, long long i) {
    if (g_is64) return (int)((const long long*)p)[i];
    return ((const int*)p)[i];
}

__global__ void probe_dtype(const long long* ei) {
    if (blockIdx.x == 0 && threadIdx.x == 0) {
        int ok64 = 1;
        for (int i = 0; i < 128; i++) {
            long long v = ei[i];
            if (v < 0 || v >= 200000) { ok64 = 0; break; }
        }
        g_is64 = ok64;
    }
}

__global__ void zero_buffers(int Nn) {
    int i = blockIdx.x * blockDim.x + threadIdx.x;
    if (i < Nn) { g_counts[i] = 0; g_fill[i] = 0; }
    if (i < NGRAPH * HID2) g_pooled[i] = 0.0f;
    if (i < NGRAPH) g_gcnt[i] = 0.0f;
}

// ---- tf32 split helper -----------------------------------------------------
__device__ __forceinline__ void tf32_split(float v, unsigned& hi, unsigned& lo) {
    asm("cvt.rna.tf32.f32 %0, %1;" : "=r"(hi) : "f"(v));
    float r = v - __uint_as_float(hi);
    asm("cvt.rna.tf32.f32 %0, %1;" : "=r"(lo) : "f"(r));
}

// ---- fuse lin1 into conv1 weight, split both B matrices --------------------
// blocks 0..127  : W12 row i = (lin1_w @ conv1_w) row, split -> g_W12hi/lo
// blocks 128..255: split conv2_w row (i-128) -> g_W2hi/lo
__global__ void fuse_w(const float* __restrict__ lin1_w,
                       const float* __restrict__ lin1_b,
                       const float* __restrict__ conv1_w,
                       const float* __restrict__ conv2_w) {
    int i = blockIdx.x, j = threadIdx.x;
    if (i < 128) {
        float s = 0.0f;
        #pragma unroll 8
        for (int k = 0; k < 128; k++) s += lin1_w[i * 128 + k] * conv1_w[k * 128 + j];
        unsigned hi, lo;
        tf32_split(s, hi, lo);
        g_W12hi[i * 128 + j] = hi;
        g_W12lo[i * 128 + j] = lo;
        if (i == 0) {
            float sb = 0.0f;
            #pragma unroll 8
            for (int k = 0; k < 128; k++) sb += lin1_b[k] * conv1_w[k * 128 + j];
            g_b12[j] = sb;
        }
    } else {
        int r = i - 128;
        if (j < 64) {
            unsigned hi, lo;
            tf32_split(conv2_w[r * 64 + j], hi, lo);
            g_W2hi[r * 64 + j] = hi;
            g_W2lo[r * 64 + j] = lo;
        }
    }
}

// ---- fused compute_dis + chunk_sums ---------------------------------------
__global__ void dis_chunksums(int Nn) {
    __shared__ int sm[256];
    int b = blockIdx.x, t = threadIdx.x;
    int s = 0;
    #pragma unroll
    for (int j = 0; j < 4; j++) {
        int idx = b * 1024 + t + j * 256;
        if (idx < Nn) {
            int c = g_counts[idx];
            s += c;
            g_dis[idx] = rsqrtf((float)(c + 1));
        }
    }
    sm[t] = s; __syncthreads();
    for (int o = 128; o > 0; o >>= 1) {
        if (t < o) sm[t] += sm[t + o];
        __syncthreads();
    }
    if (t == 0) g_chunkSum[b] = sm[0];
}

__global__ void scan_top(int nb) {
    if (threadIdx.x == 0) {
        int acc = 0;
        for (int i = 0; i < nb; i++) { g_chunkOff[i] = acc; acc += g_chunkSum[i]; }
    }
}

__global__ void scan_chunks(int Nn) {
    __shared__ int warpSums[8];
    int b = blockIdx.x, t = threadIdx.x;
    int lane = t & 31, wid = t >> 5;
    int base = b * 1024 + t * 4;
    int v[4];
    #pragma unroll
    for (int j = 0; j < 4; j++) {
        int idx = base + j;
        v[j] = (idx < Nn) ? g_counts[idx] : 0;
    }
    int s0 = v[0], s1 = s0 + v[1], s2 = s1 + v[2], s3 = s2 + v[3];
    int tot = s3;
    int xv = tot;
    #pragma unroll
    for (int o = 1; o < 32; o <<= 1) {
        int y = __shfl_up_sync(0xffffffffu, xv, o);
        if (lane >= o) xv += y;
    }
    if (lane == 31) warpSums[wid] = xv;
    __syncthreads();
    if (t == 0) {
        int acc = 0;
        for (int i = 0; i < 8; i++) { int tmp = warpSums[i]; warpSums[i] = acc; acc += tmp; }
    }
    __syncthreads();
    int off = g_chunkOff[b] + warpSums[wid] + (xv - tot);
    int pre[4] = {0, s0, s1, s2};
    #pragma unroll
    for (int j = 0; j < 4; j++) {
        int idx = base + j;
        if (idx < Nn) g_rowptr[idx] = off + pre[j];
    }
}

__global__ void fill_csr(const void* ei, int E) {
    for (int i = blockIdx.x * blockDim.x + threadIdx.x; i < E;
         i += gridDim.x * blockDim.x) {
        int src = ld_idx(ei, i);
        int dst = ld_idx(ei, (long long)E + i);
        float coef = g_dis[src] * g_dis[dst];
        int pos = g_rowptr[dst] + atomicAdd(&g_fill[dst], 1);
        g_ecsr[pos] = make_int2(src, __float_as_int(coef));
    }
}

// ---- TF32 tensor-core GEMM, B pre-split ------------------------------------
__device__ __forceinline__ void mma8(float* d, const unsigned* a, const unsigned* b) {
    asm volatile(
        "mma.sync.aligned.m16n8k8.row.col.f32.tf32.tf32.f32 "
        "{%0,%1,%2,%3}, {%4,%5,%6,%7}, {%8,%9}, {%0,%1,%2,%3};"
        : "+f"(d[0]), "+f"(d[1]), "+f"(d[2]), "+f"(d[3])
        : "r"(a[0]), "r"(a[1]), "r"(a[2]), "r"(a[3]), "r"(b[0]), "r"(b[1]));
}

// C[M,BN] = A[M,128] @ B[128,BN] (+ g_b12 if HB). 128-row tile, 256 threads.
template <int BN, bool HB>
__device__ __forceinline__ void gemm_tf32_body(const float* __restrict__ Ag,
                                               const unsigned* __restrict__ Bhi,
                                               const unsigned* __restrict__ Blo,
                                               float* __restrict__ Cg, int M,
                                               int blk) {
    constexpr int WN = (BN == 128) ? 4 : 2;
    constexpr int WM = 8 / WN;
    constexpr int MI = (128 / WM) / 16;
    constexpr int NI = 4;
    constexpr int SA = 20;
    constexpr int SB = BN + 8;

    __shared__ unsigned sAhi[128 * SA], sAlo[128 * SA];
    __shared__ unsigned sBhi[16 * SB],  sBlo[16 * SB];

    int tid = threadIdx.x, lane = tid & 31, wid = tid >> 5;
    int wm = wid % WM, wn = wid / WM;
    int row0 = blk * 128;

    float acc[MI][NI][4];
    #pragma unroll
    for (int mi = 0; mi < MI; mi++)
        #pragma unroll
        for (int ni = 0; ni < NI; ni++)
            #pragma unroll
            for (int r = 0; r < 4; r++) acc[mi][ni][r] = 0.0f;

    for (int kk = 0; kk < 128; kk += 16) {
        __syncthreads();
        // A chunk: 128 rows x 16 cols (fp32 -> hi/lo tf32)
        #pragma unroll
        for (int f = tid; f < 512; f += 256) {
            int r = f >> 2, c4 = f & 3;
            float4 v = make_float4(0.f, 0.f, 0.f, 0.f);
            if (row0 + r < M)
                v = ((const float4*)Ag)[(size_t)(row0 + r) * 32 + (kk >> 2) + c4];
            uint4 h, l;
            tf32_split(v.x, h.x, l.x); tf32_split(v.y, h.y, l.y);
            tf32_split(v.z, h.z, l.z); tf32_split(v.w, h.w, l.w);
            *(uint4*)&sAhi[r * SA + c4 * 4] = h;
            *(uint4*)&sAlo[r * SA + c4 * 4] = l;
        }
        // B chunk: pre-split, pure copy
        #pragma unroll
        for (int f = tid; f < 16 * BN / 4; f += 256) {
            int r = f / (BN / 4), c4 = f % (BN / 4);
            uint4 h = ((const uint4*)Bhi)[(size_t)(kk + r) * (BN / 4) + c4];
            uint4 l = ((const uint4*)Blo)[(size_t)(kk + r) * (BN / 4) + c4];
            *(uint4*)&sBhi[r * SB + c4 * 4] = h;
            *(uint4*)&sBlo[r * SB + c4 * 4] = l;
        }
        __syncthreads();

        #pragma unroll
        for (int ks = 0; ks < 2; ks++) {
            int kb = ks * 8;
            unsigned ahi[MI][4], alo[MI][4];
            #pragma unroll
            for (int mi = 0; mi < MI; mi++) {
                int r = wm * (MI * 16) + mi * 16 + (lane >> 2);
                int c = kb + (lane & 3);
                ahi[mi][0] = sAhi[r * SA + c];
                ahi[mi][1] = sAhi[(r + 8) * SA + c];
                ahi[mi][2] = sAhi[r * SA + c + 4];
                ahi[mi][3] = sAhi[(r + 8) * SA + c + 4];
                alo[mi][0] = sAlo[r * SA + c];
                alo[mi][1] = sAlo[(r + 8) * SA + c];
                alo[mi][2] = sAlo[r * SA + c + 4];
                alo[mi][3] = sAlo[(r + 8) * SA + c + 4];
            }
            unsigned bhi[NI][2], blo[NI][2];
            #pragma unroll
            for (int ni = 0; ni < NI; ni++) {
                int c = wn * 32 + ni * 8 + (lane >> 2);
                int r = kb + (lane & 3);
                bhi[ni][0] = sBhi[r * SB + c];
                bhi[ni][1] = sBhi[(r + 4) * SB + c];
                blo[ni][0] = sBlo[r * SB + c];
                blo[ni][1] = sBlo[(r + 4) * SB + c];
            }
            #pragma unroll
            for (int mi = 0; mi < MI; mi++)
                #pragma unroll
                for (int ni = 0; ni < NI; ni++) mma8(acc[mi][ni], ahi[mi], bhi[ni]);
            #pragma unroll
            for (int mi = 0; mi < MI; mi++)
                #pragma unroll
                for (int ni = 0; ni < NI; ni++) mma8(acc[mi][ni], ahi[mi], blo[ni]);
            #pragma unroll
            for (int mi = 0; mi < MI; mi++)
                #pragma unroll
                for (int ni = 0; ni < NI; ni++) mma8(acc[mi][ni], alo[mi], bhi[ni]);
        }
    }

    #pragma unroll
    for (int mi = 0; mi < MI; mi++) {
        int r = row0 + wm * (MI * 16) + mi * 16 + (lane >> 2);
        #pragma unroll
        for (int ni = 0; ni < NI; ni++) {
            int c = wn * 32 + ni * 8 + (lane & 3) * 2;
            float bx = 0.f, by = 0.f;
            if (HB) { bx = g_b12[c]; by = g_b12[c + 1]; }
            float2 v0 = make_float2(acc[mi][ni][0] + bx, acc[mi][ni][1] + by);
            float2 v1 = make_float2(acc[mi][ni][2] + bx, acc[mi][ni][3] + by);
            if (r < M)     *(float2*)&Cg[(size_t)r * BN + c] = v0;
            if (r + 8 < M) *(float2*)&Cg[(size_t)(r + 8) * BN + c] = v1;
        }
    }
}

// ---- GEMM1 grid-fused with count_dst ---------------------------------------
#define COUNT_BLOCKS 256
__global__ __launch_bounds__(256) void gemm1_count_kernel(
    const float* __restrict__ x, const void* __restrict__ ei,
    int M, int E, int nGemmBlocks) {
    if ((int)blockIdx.x < nGemmBlocks) {
        gemm_tf32_body<128, true>(x, g_W12hi, g_W12lo, g_t1, M, blockIdx.x);
    } else {
        int b = blockIdx.x - nGemmBlocks;
        int stride = COUNT_BLOCKS * 256;
        for (int i = b * 256 + threadIdx.x; i < E; i += stride) {
            int dst = ld_idx(ei, (long long)E + i);
            atomicAdd(&g_counts[dst], 1);
        }
    }
}

__global__ __launch_bounds__(256) void gemm2_kernel(int M) {
    gemm_tf32_body<64, false>(g_h1, g_W2hi, g_W2lo, g_t2, M, blockIdx.x);
}

// ---- conv1 gather ----------------------------------------------------------
__global__ void gather_conv1(const float* __restrict__ conv1_b,
                             const float* __restrict__ drop_u, int Nn) {
    int warp = (blockIdx.x * blockDim.x + threadIdx.x) >> 5;
    if (warp >= Nn) return;
    int lane = threadIdx.x & 31;
    int i = warp;
    const float4* tb = (const float4*)g_t1;

    float4 acc = ((const float4*)conv1_b)[lane];
    float d = g_dis[i];
    float dsq = d * d;
    float4 v = tb[(size_t)i * 32 + lane];
    acc.x += dsq * v.x; acc.y += dsq * v.y; acc.z += dsq * v.z; acc.w += dsq * v.w;

    int s = g_rowptr[i], e = s + g_counts[i];
    #pragma unroll 4
    for (int j = s; j < e; j++) {
        int2 ed = __ldg(&g_ecsr[j]);
        float c = __int_as_float(ed.y);
        float4 w = tb[(size_t)ed.x * 32 + lane];
        acc.x += c * w.x; acc.y += c * w.y; acc.z += c * w.z; acc.w += c * w.w;
    }

    float4 u = ((const float4*)drop_u)[(size_t)i * 32 + lane];
    float4 o;
    o.x = (u.x >= 0.5f) ? fmaxf(acc.x, 0.f) * 2.f : 0.f;
    o.y = (u.y >= 0.5f) ? fmaxf(acc.y, 0.f) * 2.f : 0.f;
    o.z = (u.z >= 0.5f) ? fmaxf(acc.z, 0.f) * 2.f : 0.f;
    o.w = (u.w >= 0.5f) ? fmaxf(acc.w, 0.f) * 2.f : 0.f;
    ((float4*)g_h1)[(size_t)i * 32 + lane] = o;
}

// ---- conv2 gather + mean-pool ----------------------------------------------
__global__ void gather_conv2_pool(const float* __restrict__ conv2_b,
                                  const void* __restrict__ batch, int Nn) {
    int warp = (blockIdx.x * blockDim.x + threadIdx.x) >> 5;
    if (warp >= Nn) return;
    int lane = threadIdx.x & 31;
    int i = warp;
    const float2* tb = (const float2*)g_t2;

    float2 acc = ((const float2*)conv2_b)[lane];
    float d = g_dis[i];
    float dsq = d * d;
    float2 v = tb[(size_t)i * 32 + lane];
    acc.x += dsq * v.x; acc.y += dsq * v.y;

    int s = g_rowptr[i], e = s + g_counts[i];
    #pragma unroll 4
    for (int j = s; j < e; j++) {
        int2 ed = __ldg(&g_ecsr[j]);
        float c = __int_as_float(ed.y);
        float2 w = tb[(size_t)ed.x * 32 + lane];
        acc.x += c * w.x; acc.y += c * w.y;
    }

    int g = ld_idx(batch, i);
    atomicAdd(&g_pooled[g * HID2 + lane * 2], acc.x);
    atomicAdd(&g_pooled[g * HID2 + lane * 2 + 1], acc.y);
    if (lane == 0) atomicAdd(&g_gcnt[g], 1.0f);
}

__global__ void final_lin(const float* __restrict__ lin2_w,
                          const float* __restrict__ lin2_b,
                          float* __restrict__ out) {
    int g = blockIdx.x;
    int c = threadIdx.x;
    if (c >= NCLS) return;
    float inv = 1.0f / fmaxf(g_gcnt[g], 1.0f);
    float s = lin2_b[c];
    #pragma unroll
    for (int dd = 0; dd < HID2; dd++)
        s += g_pooled[g * HID2 + dd] * inv * lin2_w[dd * NCLS + c];
    out[g * NCLS + c] = s;
}

// ---------------------------------------------------------------------------
extern "C" void kernel_launch(void* const* d_in, const int* in_sizes, int n_in,
                              void* d_out, int out_size) {
    const float* x     = (const float*)d_in[0];
    const void*  ei    = d_in[1];
    const void*  batch = d_in[2];
    int idx = 3;
    if (n_in >= 13 && in_sizes[3] == 1) idx = 4;
    const float* drop_u  = (const float*)d_in[idx++];
    const float* lin1_w  = (const float*)d_in[idx++];
    const float* lin1_b  = (const float*)d_in[idx++];
    const float* conv1_w = (const float*)d_in[idx++];
    const float* conv1_b = (const float*)d_in[idx++];
    const float* conv2_w = (const float*)d_in[idx++];
    const float* conv2_b = (const float*)d_in[idx++];
    const float* lin2_w  = (const float*)d_in[idx++];
    const float* lin2_b  = (const float*)d_in[idx++];
    float* out = (float*)d_out;

    int Nn = in_sizes[0] / 128;
    int E  = in_sizes[1] / 2;
    if (Nn > 100000) Nn = 100000;
    if (E > E_CAP) E = E_CAP;
    int nb = (Nn + 1023) / 1024;
    int gb1 = (Nn + 127) / 128;

    // launch #4 = fused gemm1+count -> lands in the ncu -s 5 -c 1 window
    zero_buffers<<<(Nn + 255) / 256, 256>>>(Nn);
    fuse_w<<<256, 128>>>(lin1_w, lin1_b, conv1_w, conv2_w);
    probe_dtype<<<1, 1>>>((const long long*)ei);
    gemm1_count_kernel<<<gb1 + COUNT_BLOCKS, 256>>>(x, ei, Nn, E, gb1);
    dis_chunksums<<<nb, 256>>>(Nn);
    scan_top<<<1, 1>>>(nb);
    scan_chunks<<<nb, 256>>>(Nn);
    fill_csr<<<2048, 256>>>(ei, E);
    gather_conv1<<<(Nn * 32 + 255) / 256, 256>>>(conv1_b, drop_u, Nn);
    gemm2_kernel<<<(Nn + 127) / 128, 256>>>(Nn);
    gather_conv2_pool<<<(Nn * 32 + 255) / 256, 256>>>(conv2_b, batch, Nn);
    final_lin<<<NGRAPH, 32>>>(lin2_w, lin2_b, out);
}

// round 11
// speedup vs baseline: 1.3377x; 1.0721x over previous
#include <cuda_runtime.h>

// ---------------------------------------------------------------------------
// GCN forward on GB300.  Round 10:
//  - Stream fork (CSR chain || fuse_w->GEMM1) with LAZY stream creation inside
//    kernel_launch (first, non-captured call) + serial fallback = R7 schedule.
//  - GEMMs: register-prefetch pipeline hides global-A latency under MMAs.
//  - scan_top folded into scan_chunks (per-block reduction over chunk sums).
// GEMMs: mma.sync.m16n8k8 tf32, 3-term compensation (fp32-grade accuracy).
// ---------------------------------------------------------------------------

#define NN_CAP 100352
#define E_CAP  1600000
#define NGRAPH 128
#define HID    128
#define HID2   64
#define NCLS   10

__device__ int      g_is64;
__device__ int      g_counts[NN_CAP];
__device__ int      g_rowptr[NN_CAP];
__device__ int      g_fill[NN_CAP];
__device__ int      g_chunkSum[256];
__device__ float    g_dis[NN_CAP];
__device__ int2     g_ecsr[E_CAP];
__device__ unsigned g_W12hi[128*128], g_W12lo[128*128];
__device__ unsigned g_W2hi[128*64],  g_W2lo[128*64];
__device__ float    g_b12[128];
__device__ float    g_t1[100000*128];
__device__ float    g_h1[100000*128];
__device__ float    g_t2[100000*64];
__device__ float    g_pooled[NGRAPH*HID2];
__device__ float    g_gcnt[NGRAPH];

// ---- index loading (int64 vs int32 decided at runtime) ---------------------
__device__ __forceinline__ int ld_idx(const void* p, long long i) {
    if (g_is64) return (int)((const long long*)p)[i];
    return ((const int*)p)[i];
}

__global__ void probe_dtype(const long long* ei) {
    if (blockIdx.x == 0 && threadIdx.x == 0) {
        int ok64 = 1;
        for (int i = 0; i < 128; i++) {
            long long v = ei[i];
            if (v < 0 || v >= 200000) { ok64 = 0; break; }
        }
        g_is64 = ok64;
    }
}

__global__ void zero_buffers(int Nn) {
    int i = blockIdx.x * blockDim.x + threadIdx.x;
    if (i < Nn) { g_counts[i] = 0; g_fill[i] = 0; }
    if (i < NGRAPH * HID2) g_pooled[i] = 0.0f;
    if (i < NGRAPH) g_gcnt[i] = 0.0f;
}

__global__ void count_dst(const void* ei, int E) {
    for (int i = blockIdx.x * blockDim.x + threadIdx.x; i < E;
         i += gridDim.x * blockDim.x) {
        int dst = ld_idx(ei, (long long)E + i);
        atomicAdd(&g_counts[dst], 1);
    }
}

// ---- tf32 split helper -----------------------------------------------------
__device__ __forceinline__ void tf32_split(float v, unsigned& hi, unsigned& lo) {
    asm("cvt.rna.tf32.f32 %0, %1;" : "=r"(hi) : "f"(v));
    float r = v - __uint_as_float(hi);
    asm("cvt.rna.tf32.f32 %0, %1;" : "=r"(lo) : "f"(r));
}

// ---- fuse lin1 into conv1 weight, split both B matrices --------------------
__global__ void fuse_w(const float* __restrict__ lin1_w,
                       const float* __restrict__ lin1_b,
                       const float* __restrict__ conv1_w,
                       const float* __restrict__ conv2_w) {
    int i = blockIdx.x, j = threadIdx.x;
    if (i < 128) {
        float s = 0.0f;
        #pragma unroll 8
        for (int k = 0; k < 128; k++) s += lin1_w[i * 128 + k] * conv1_w[k * 128 + j];
        unsigned hi, lo;
        tf32_split(s, hi, lo);
        g_W12hi[i * 128 + j] = hi;
        g_W12lo[i * 128 + j] = lo;
        if (i == 0) {
            float sb = 0.0f;
            #pragma unroll 8
            for (int k = 0; k < 128; k++) sb += lin1_b[k] * conv1_w[k * 128 + j];
            g_b12[j] = sb;
        }
    } else {
        int r = i - 128;
        if (j < 64) {
            unsigned hi, lo;
            tf32_split(conv2_w[r * 64 + j], hi, lo);
            g_W2hi[r * 64 + j] = hi;
            g_W2lo[r * 64 + j] = lo;
        }
    }
}

// ---- fused compute_dis + chunk_sums ---------------------------------------
__global__ void dis_chunksums(int Nn) {
    __shared__ int sm[256];
    int b = blockIdx.x, t = threadIdx.x;
    int s = 0;
    #pragma unroll
    for (int j = 0; j < 4; j++) {
        int idx = b * 1024 + t + j * 256;
        if (idx < Nn) {
            int c = g_counts[idx];
            s += c;
            g_dis[idx] = rsqrtf((float)(c + 1));
        }
    }
    sm[t] = s; __syncthreads();
    for (int o = 128; o > 0; o >>= 1) {
        if (t < o) sm[t] += sm[t + o];
        __syncthreads();
    }
    if (t == 0) g_chunkSum[b] = sm[0];
}

// ---- scan_chunks with inline top-scan (per-block reduction) ----------------
__global__ void scan_chunks(int Nn) {
    __shared__ int warpSums[8];
    __shared__ int smTop[256];
    int b = blockIdx.x, t = threadIdx.x;
    int lane = t & 31, wid = t >> 5;

    // chunk offset for this block = sum of chunkSum[0..b)
    smTop[t] = (t < b) ? g_chunkSum[t] : 0;
    __syncthreads();
    for (int o = 128; o > 0; o >>= 1) {
        if (t < o) smTop[t] += smTop[t + o];
        __syncthreads();
    }
    int chunkOff = smTop[0];
    __syncthreads();

    int base = b * 1024 + t * 4;
    int v[4];
    #pragma unroll
    for (int j = 0; j < 4; j++) {
        int idx = base + j;
        v[j] = (idx < Nn) ? g_counts[idx] : 0;
    }
    int s0 = v[0], s1 = s0 + v[1], s2 = s1 + v[2], s3 = s2 + v[3];
    int tot = s3;
    int xv = tot;
    #pragma unroll
    for (int o = 1; o < 32; o <<= 1) {
        int y = __shfl_up_sync(0xffffffffu, xv, o);
        if (lane >= o) xv += y;
    }
    if (lane == 31) warpSums[wid] = xv;
    __syncthreads();
    if (t == 0) {
        int acc = 0;
        for (int i = 0; i < 8; i++) { int tmp = warpSums[i]; warpSums[i] = acc; acc += tmp; }
    }
    __syncthreads();
    int off = chunkOff + warpSums[wid] + (xv - tot);
    int pre[4] = {0, s0, s1, s2};
    #pragma unroll
    for (int j = 0; j < 4; j++) {
        int idx = base + j;
        if (idx < Nn) g_rowptr[idx] = off + pre[j];
    }
}

__global__ void fill_csr(const void* ei, int E) {
    for (int i = blockIdx.x * blockDim.x + threadIdx.x; i < E;
         i += gridDim.x * blockDim.x) {
        int src = ld_idx(ei, i);
        int dst = ld_idx(ei, (long long)E + i);
        float coef = g_dis[src] * g_dis[dst];
        int pos = g_rowptr[dst] + atomicAdd(&g_fill[dst], 1);
        g_ecsr[pos] = make_int2(src, __float_as_int(coef));
    }
}

// ---- TF32 tensor-core GEMM, B pre-split, A register-prefetch pipeline ------
__device__ __forceinline__ void mma8(float* d, const unsigned* a, const unsigned* b) {
    asm volatile(
        "mma.sync.aligned.m16n8k8.row.col.f32.tf32.tf32.f32 "
        "{%0,%1,%2,%3}, {%4,%5,%6,%7}, {%8,%9}, {%0,%1,%2,%3};"
        : "+f"(d[0]), "+f"(d[1]), "+f"(d[2]), "+f"(d[3])
        : "r"(a[0]), "r"(a[1]), "r"(a[2]), "r"(a[3]), "r"(b[0]), "r"(b[1]));
}

template <int BN, bool HB>
__device__ __forceinline__ void gemm_tf32_body(const float* __restrict__ Ag,
                                               const unsigned* __restrict__ Bhi,
                                               const unsigned* __restrict__ Blo,
                                               float* __restrict__ Cg, int M,
                                               int blk) {
    constexpr int WN = (BN == 128) ? 4 : 2;
    constexpr int WM = 8 / WN;
    constexpr int MI = (128 / WM) / 16;
    constexpr int NI = 4;
    constexpr int SA = 20;
    constexpr int SB = BN + 8;
    constexpr int NB = BN / 64;            // B uint4 loads per thread (2 or 1)

    __shared__ unsigned sAhi[128 * SA], sAlo[128 * SA];
    __shared__ unsigned sBhi[16 * SB],  sBlo[16 * SB];

    int tid = threadIdx.x, lane = tid & 31, wid = tid >> 5;
    int wm = wid % WM, wn = wid / WM;
    int row0 = blk * 128;

    // A prefetch state: thread handles staging elements f=tid and f=tid+256
    const float4* A4 = (const float4*)Ag;
    int rA0 = tid >> 2,          cA0 = tid & 3;
    int rA1 = (tid + 256) >> 2,  cA1 = (tid + 256) & 3;
    bool vA0 = (row0 + rA0) < M, vA1 = (row0 + rA1) < M;
    const float4 z4 = make_float4(0.f, 0.f, 0.f, 0.f);
    float4 pa0 = vA0 ? A4[(size_t)(row0 + rA0) * 32 + cA0] : z4;
    float4 pa1 = vA1 ? A4[(size_t)(row0 + rA1) * 32 + cA1] : z4;

    float acc[MI][NI][4];
    #pragma unroll
    for (int mi = 0; mi < MI; mi++)
        #pragma unroll
        for (int ni = 0; ni < NI; ni++)
            #pragma unroll
            for (int r = 0; r < 4; r++) acc[mi][ni][r] = 0.0f;

    for (int kk = 0; kk < 128; kk += 16) {
        __syncthreads();
        // B loads first (L2-resident weights) so they overlap A conversion
        uint4 pbh[NB], pbl[NB];
        #pragma unroll
        for (int i = 0; i < NB; i++) {
            int idx = tid + i * 256;
            int rB = idx / (BN / 4), cB = idx % (BN / 4);
            pbh[i] = ((const uint4*)Bhi)[(size_t)(kk + rB) * (BN / 4) + cB];
            pbl[i] = ((const uint4*)Blo)[(size_t)(kk + rB) * (BN / 4) + cB];
        }
        // A: convert prefetched registers, store to smem
        {
            uint4 h, l;
            tf32_split(pa0.x, h.x, l.x); tf32_split(pa0.y, h.y, l.y);
            tf32_split(pa0.z, h.z, l.z); tf32_split(pa0.w, h.w, l.w);
            *(uint4*)&sAhi[rA0 * SA + cA0 * 4] = h;
            *(uint4*)&sAlo[rA0 * SA + cA0 * 4] = l;
            tf32_split(pa1.x, h.x, l.x); tf32_split(pa1.y, h.y, l.y);
            tf32_split(pa1.z, h.z, l.z); tf32_split(pa1.w, h.w, l.w);
            *(uint4*)&sAhi[rA1 * SA + cA1 * 4] = h;
            *(uint4*)&sAlo[rA1 * SA + cA1 * 4] = l;
        }
        // B stores
        #pragma unroll
        for (int i = 0; i < NB; i++) {
            int idx = tid + i * 256;
            int rB = idx / (BN / 4), cB = idx % (BN / 4);
            *(uint4*)&sBhi[rB * SB + cB * 4] = pbh[i];
            *(uint4*)&sBlo[rB * SB + cB * 4] = pbl[i];
        }
        __syncthreads();

        // prefetch next A chunk; latency hides under the MMA section below
        if (kk < 112) {
            int co = (kk >> 2) + 4;
            pa0 = vA0 ? A4[(size_t)(row0 + rA0) * 32 + co + cA0] : z4;
            pa1 = vA1 ? A4[(size_t)(row0 + rA1) * 32 + co + cA1] : z4;
        }

        #pragma unroll
        for (int ks = 0; ks < 2; ks++) {
            int kb = ks * 8;
            unsigned ahi[MI][4], alo[MI][4];
            #pragma unroll
            for (int mi = 0; mi < MI; mi++) {
                int r = wm * (MI * 16) + mi * 16 + (lane >> 2);
                int c = kb + (lane & 3);
                ahi[mi][0] = sAhi[r * SA + c];
                ahi[mi][1] = sAhi[(r + 8) * SA + c];
                ahi[mi][2] = sAhi[r * SA + c + 4];
                ahi[mi][3] = sAhi[(r + 8) * SA + c + 4];
                alo[mi][0] = sAlo[r * SA + c];
                alo[mi][1] = sAlo[(r + 8) * SA + c];
                alo[mi][2] = sAlo[r * SA + c + 4];
                alo[mi][3] = sAlo[(r + 8) * SA + c + 4];
            }
            unsigned bhi[NI][2], blo[NI][2];
            #pragma unroll
            for (int ni = 0; ni < NI; ni++) {
                int c = wn * 32 + ni * 8 + (lane >> 2);
                int r = kb + (lane & 3);
                bhi[ni][0] = sBhi[r * SB + c];
                bhi[ni][1] = sBhi[(r + 4) * SB + c];
                blo[ni][0] = sBlo[r * SB + c];
                blo[ni][1] = sBlo[(r + 4) * SB + c];
            }
            #pragma unroll
            for (int mi = 0; mi < MI; mi++)
                #pragma unroll
                for (int ni = 0; ni < NI; ni++) mma8(acc[mi][ni], ahi[mi], bhi[ni]);
            #pragma unroll
            for (int mi = 0; mi < MI; mi++)
                #pragma unroll
                for (int ni = 0; ni < NI; ni++) mma8(acc[mi][ni], ahi[mi], blo[ni]);
            #pragma unroll
            for (int mi = 0; mi < MI; mi++)
                #pragma unroll
                for (int ni = 0; ni < NI; ni++) mma8(acc[mi][ni], alo[mi], bhi[ni]);
        }
    }

    #pragma unroll
    for (int mi = 0; mi < MI; mi++) {
        int r = row0 + wm * (MI * 16) + mi * 16 + (lane >> 2);
        #pragma unroll
        for (int ni = 0; ni < NI; ni++) {
            int c = wn * 32 + ni * 8 + (lane & 3) * 2;
            float bx = 0.f, by = 0.f;
            if (HB) { bx = g_b12[c]; by = g_b12[c + 1]; }
            float2 v0 = make_float2(acc[mi][ni][0] + bx, acc[mi][ni][1] + by);
            float2 v1 = make_float2(acc[mi][ni][2] + bx, acc[mi][ni][3] + by);
            if (r < M)     *(float2*)&Cg[(size_t)r * BN + c] = v0;
            if (r + 8 < M) *(float2*)&Cg[(size_t)(r + 8) * BN + c] = v1;
        }
    }
}

__global__ __launch_bounds__(256, 2) void gemm1_kernel(const float* __restrict__ x, int M) {
    gemm_tf32_body<128, true>(x, g_W12hi, g_W12lo, g_t1, M, blockIdx.x);
}

// fallback-path variant: gemm1 with count_dst fused into extra blocks
#define COUNT_BLOCKS 256
__global__ __launch_bounds__(256, 2) void gemm1_count_kernel(
    const float* __restrict__ x, const void* __restrict__ ei,
    int M, int E, int nGemmBlocks) {
    if ((int)blockIdx.x < nGemmBlocks) {
        gemm_tf32_body<128, true>(x, g_W12hi, g_W12lo, g_t1, M, blockIdx.x);
    } else {
        int b = blockIdx.x - nGemmBlocks;
        int stride = COUNT_BLOCKS * 256;
        for (int i = b * 256 + threadIdx.x; i < E; i += stride) {
            int dst = ld_idx(ei, (long long)E + i);
            atomicAdd(&g_counts[dst], 1);
        }
    }
}

__global__ __launch_bounds__(256, 2) void gemm2_kernel(int M) {
    gemm_tf32_body<64, false>(g_h1, g_W2hi, g_W2lo, g_t2, M, blockIdx.x);
}

// ---- conv1 gather ----------------------------------------------------------
__global__ void gather_conv1(const float* __restrict__ conv1_b,
                             const float* __restrict__ drop_u, int Nn) {
    int warp = (blockIdx.x * blockDim.x + threadIdx.x) >> 5;
    if (warp >= Nn) return;
    int lane = threadIdx.x & 31;
    int i = warp;
    const float4* tb = (const float4*)g_t1;

    float4 acc = ((const float4*)conv1_b)[lane];
    float d = g_dis[i];
    float dsq = d * d;
    float4 v = tb[(size_t)i * 32 + lane];
    acc.x += dsq * v.x; acc.y += dsq * v.y; acc.z += dsq * v.z; acc.w += dsq * v.w;

    int s = g_rowptr[i], e = s + g_counts[i];
    #pragma unroll 4
    for (int j = s; j < e; j++) {
        int2 ed = __ldg(&g_ecsr[j]);
        float c = __int_as_float(ed.y);
        float4 w = tb[(size_t)ed.x * 32 + lane];
        acc.x += c * w.x; acc.y += c * w.y; acc.z += c * w.z; acc.w += c * w.w;
    }

    float4 u = ((const float4*)drop_u)[(size_t)i * 32 + lane];
    float4 o;
    o.x = (u.x >= 0.5f) ? fmaxf(acc.x, 0.f) * 2.f : 0.f;
    o.y = (u.y >= 0.5f) ? fmaxf(acc.y, 0.f) * 2.f : 0.f;
    o.z = (u.z >= 0.5f) ? fmaxf(acc.z, 0.f) * 2.f : 0.f;
    o.w = (u.w >= 0.5f) ? fmaxf(acc.w, 0.f) * 2.f : 0.f;
    ((float4*)g_h1)[(size_t)i * 32 + lane] = o;
}

// ---- conv2 gather + mean-pool ----------------------------------------------
__global__ void gather_conv2_pool(const float* __restrict__ conv2_b,
                                  const void* __restrict__ batch, int Nn) {
    int warp = (blockIdx.x * blockDim.x + threadIdx.x) >> 5;
    if (warp >= Nn) return;
    int lane = threadIdx.x & 31;
    int i = warp;
    const float2* tb = (const float2*)g_t2;

    float2 acc = ((const float2*)conv2_b)[lane];
    float d = g_dis[i];
    float dsq = d * d;
    float2 v = tb[(size_t)i * 32 + lane];
    acc.x += dsq * v.x; acc.y += dsq * v.y;

    int s = g_rowptr[i], e = s + g_counts[i];
    #pragma unroll 4
    for (int j = s; j < e; j++) {
        int2 ed = __ldg(&g_ecsr[j]);
        float c = __int_as_float(ed.y);
        float2 w = tb[(size_t)ed.x * 32 + lane];
        acc.x += c * w.x; acc.y += c * w.y;
    }

    int g = ld_idx(batch, i);
    atomicAdd(&g_pooled[g * HID2 + lane * 2], acc.x);
    atomicAdd(&g_pooled[g * HID2 + lane * 2 + 1], acc.y);
    if (lane == 0) atomicAdd(&g_gcnt[g], 1.0f);
}

__global__ void final_lin(const float* __restrict__ lin2_w,
                          const float* __restrict__ lin2_b,
                          float* __restrict__ out) {
    int g = blockIdx.x;
    int c = threadIdx.x;
    if (c >= NCLS) return;
    float inv = 1.0f / fmaxf(g_gcnt[g], 1.0f);
    float s = lin2_b[c];
    #pragma unroll
    for (int dd = 0; dd < HID2; dd++)
        s += g_pooled[g * HID2 + dd] * inv * lin2_w[dd * NCLS + c];
    out[g * NCLS + c] = s;
}

// ---- lazy stream/event creation (first call = eager correctness run,
//      after harness device setup, before graph capture) ---------------------
static int          g_streamState = 0;   // 0 untried, 1 ok, -1 failed
static cudaStream_t g_s1;
static cudaEvent_t  g_ev0, g_ev1;

// ---------------------------------------------------------------------------
extern "C" void kernel_launch(void* const* d_in, const int* in_sizes, int n_in,
                              void* d_out, int out_size) {
    const float* x     = (const float*)d_in[0];
    const void*  ei    = d_in[1];
    const void*  batch = d_in[2];
    int idx = 3;
    if (n_in >= 13 && in_sizes[3] == 1) idx = 4;
    const float* drop_u  = (const float*)d_in[idx++];
    const float* lin1_w  = (const float*)d_in[idx++];
    const float* lin1_b  = (const float*)d_in[idx++];
    const float* conv1_w = (const float*)d_in[idx++];
    const float* conv1_b = (const float*)d_in[idx++];
    const float* conv2_w = (const float*)d_in[idx++];
    const float* conv2_b = (const float*)d_in[idx++];
    const float* lin2_w  = (const float*)d_in[idx++];
    const float* lin2_b  = (const float*)d_in[idx++];
    float* out = (float*)d_out;

    int Nn = in_sizes[0] / 128;
    int E  = in_sizes[1] / 2;
    if (Nn > 100000) Nn = 100000;
    if (E > E_CAP) E = E_CAP;
    int nb = (Nn + 1023) / 1024;
    int gb1 = (Nn + 127) / 128;

    if (g_streamState == 0) {
        bool ok =
            cudaStreamCreateWithFlags(&g_s1, cudaStreamNonBlocking) == cudaSuccess &&
            cudaEventCreateWithFlags(&g_ev0, cudaEventDisableTiming) == cudaSuccess &&
            cudaEventCreateWithFlags(&g_ev1, cudaEventDisableTiming) == cudaSuccess;
        g_streamState = ok ? 1 : -1;
    }
    bool fork = (g_streamState == 1);
    cudaStream_t s0 = 0;

    if (fork) {
        // s0: zero(1) probe(2) fuse_w(3) gemm1(4 -> ncu window)
        zero_buffers<<<(Nn + 255) / 256, 256, 0, s0>>>(Nn);
        probe_dtype<<<1, 1, 0, s0>>>((const long long*)ei);
        cudaEventRecord(g_ev0, s0);
        fuse_w<<<256, 128, 0, s0>>>(lin1_w, lin1_b, conv1_w, conv2_w);
        gemm1_kernel<<<gb1, 256, 0, s0>>>(x, Nn);

        // s1: CSR chain concurrent with fuse_w+gemm1
        cudaStreamWaitEvent(g_s1, g_ev0, 0);
        count_dst<<<1024, 256, 0, g_s1>>>(ei, E);
        dis_chunksums<<<nb, 256, 0, g_s1>>>(Nn);
        scan_chunks<<<nb, 256, 0, g_s1>>>(Nn);
        fill_csr<<<2048, 256, 0, g_s1>>>(ei, E);
        cudaEventRecord(g_ev1, g_s1);
        cudaStreamWaitEvent(s0, g_ev1, 0);
    } else {
        // serial fallback = R7 schedule (count fused into gemm1 launch)
        zero_buffers<<<(Nn + 255) / 256, 256, 0, s0>>>(Nn);
        probe_dtype<<<1, 1, 0, s0>>>((const long long*)ei);
        fuse_w<<<256, 128, 0, s0>>>(lin1_w, lin1_b, conv1_w, conv2_w);
        gemm1_count_kernel<<<gb1 + COUNT_BLOCKS, 256, 0, s0>>>(x, ei, Nn, E, gb1);
        dis_chunksums<<<nb, 256, 0, s0>>>(Nn);
        scan_chunks<<<nb, 256, 0, s0>>>(Nn);
        fill_csr<<<2048, 256, 0, s0>>>(ei, E);
    }

    // join, serial tail on s0
    gather_conv1<<<(Nn * 32 + 255) / 256, 256, 0, s0>>>(conv1_b, drop_u, Nn);
    gemm2_kernel<<<(Nn + 127) / 128, 256, 0, s0>>>(Nn);
    gather_conv2_pool<<<(Nn * 32 + 255) / 256, 256, 0, s0>>>(conv2_b, batch, Nn);
    final_lin<<<NGRAPH, 32, 0, s0>>>(lin2_w, lin2_b, out);
}

// round 12
// speedup vs baseline: 1.3734x; 1.0267x over previous
#include <cuda_runtime.h>
#include <cuda_fp16.h>

// ---------------------------------------------------------------------------
// GCN forward on GB300.  Round 12:
//  - t1/t2 (gather sources) stored as fp16: halves gather L2 traffic, which
//    was the dominant remaining block (~100us at the LTS cap). Accumulation
//    stays fp32; expected rel_err ~3e-4 (threshold 1e-3).
//  - Keeps: stream fork (CSR || GEMM1), A register-prefetch GEMM pipeline,
//    merged scan, pre-split tf32 B, 3-term tf32 compensation.
// ---------------------------------------------------------------------------

#define NN_CAP 100352
#define E_CAP  1600000
#define NGRAPH 128
#define HID    128
#define HID2   64
#define NCLS   10

__device__ int      g_is64;
__device__ int      g_counts[NN_CAP];
__device__ int      g_rowptr[NN_CAP];
__device__ int      g_fill[NN_CAP];
__device__ int      g_chunkSum[256];
__device__ float    g_dis[NN_CAP];
__device__ int2     g_ecsr[E_CAP];
__device__ unsigned g_W12hi[128*128], g_W12lo[128*128];
__device__ unsigned g_W2hi[128*64],  g_W2lo[128*64];
__device__ float    g_b12[128];
__device__ __half   g_t1[100000*128];     // fp16 gather source (conv1)
__device__ float    g_h1[100000*128];
__device__ __half   g_t2[100000*64];      // fp16 gather source (conv2)
__device__ float    g_pooled[NGRAPH*HID2];
__device__ float    g_gcnt[NGRAPH];

// ---- index loading (int64 vs int32 decided at runtime) ---------------------
__device__ __forceinline__ int ld_idx(const void* p, long long i) {
    if (g_is64) return (int)((const long long*)p)[i];
    return ((const int*)p)[i];
}

__global__ void probe_dtype(const long long* ei) {
    if (blockIdx.x == 0 && threadIdx.x == 0) {
        int ok64 = 1;
        for (int i = 0; i < 128; i++) {
            long long v = ei[i];
            if (v < 0 || v >= 200000) { ok64 = 0; break; }
        }
        g_is64 = ok64;
    }
}

__global__ void zero_buffers(int Nn) {
    int i = blockIdx.x * blockDim.x + threadIdx.x;
    if (i < Nn) { g_counts[i] = 0; g_fill[i] = 0; }
    if (i < NGRAPH * HID2) g_pooled[i] = 0.0f;
    if (i < NGRAPH) g_gcnt[i] = 0.0f;
}

__global__ void count_dst(const void* ei, int E) {
    for (int i = blockIdx.x * blockDim.x + threadIdx.x; i < E;
         i += gridDim.x * blockDim.x) {
        int dst = ld_idx(ei, (long long)E + i);
        atomicAdd(&g_counts[dst], 1);
    }
}

// ---- tf32 split helper -----------------------------------------------------
__device__ __forceinline__ void tf32_split(float v, unsigned& hi, unsigned& lo) {
    asm("cvt.rna.tf32.f32 %0, %1;" : "=r"(hi) : "f"(v));
    float r = v - __uint_as_float(hi);
    asm("cvt.rna.tf32.f32 %0, %1;" : "=r"(lo) : "f"(r));
}

// ---- fuse lin1 into conv1 weight, split both B matrices --------------------
__global__ void fuse_w(const float* __restrict__ lin1_w,
                       const float* __restrict__ lin1_b,
                       const float* __restrict__ conv1_w,
                       const float* __restrict__ conv2_w) {
    int i = blockIdx.x, j = threadIdx.x;
    if (i < 128) {
        float s = 0.0f;
        #pragma unroll 8
        for (int k = 0; k < 128; k++) s += lin1_w[i * 128 + k] * conv1_w[k * 128 + j];
        unsigned hi, lo;
        tf32_split(s, hi, lo);
        g_W12hi[i * 128 + j] = hi;
        g_W12lo[i * 128 + j] = lo;
        if (i == 0) {
            float sb = 0.0f;
            #pragma unroll 8
            for (int k = 0; k < 128; k++) sb += lin1_b[k] * conv1_w[k * 128 + j];
            g_b12[j] = sb;
        }
    } else {
        int r = i - 128;
        if (j < 64) {
            unsigned hi, lo;
            tf32_split(conv2_w[r * 64 + j], hi, lo);
            g_W2hi[r * 64 + j] = hi;
            g_W2lo[r * 64 + j] = lo;
        }
    }
}

// ---- fused compute_dis + chunk_sums ---------------------------------------
__global__ void dis_chunksums(int Nn) {
    __shared__ int sm[256];
    int b = blockIdx.x, t = threadIdx.x;
    int s = 0;
    #pragma unroll
    for (int j = 0; j < 4; j++) {
        int idx = b * 1024 + t + j * 256;
        if (idx < Nn) {
            int c = g_counts[idx];
            s += c;
            g_dis[idx] = rsqrtf((float)(c + 1));
        }
    }
    sm[t] = s; __syncthreads();
    for (int o = 128; o > 0; o >>= 1) {
        if (t < o) sm[t] += sm[t + o];
        __syncthreads();
    }
    if (t == 0) g_chunkSum[b] = sm[0];
}

// ---- scan_chunks with inline top-scan --------------------------------------
__global__ void scan_chunks(int Nn) {
    __shared__ int warpSums[8];
    __shared__ int smTop[256];
    int b = blockIdx.x, t = threadIdx.x;
    int lane = t & 31, wid = t >> 5;

    smTop[t] = (t < b) ? g_chunkSum[t] : 0;
    __syncthreads();
    for (int o = 128; o > 0; o >>= 1) {
        if (t < o) smTop[t] += smTop[t + o];
        __syncthreads();
    }
    int chunkOff = smTop[0];
    __syncthreads();

    int base = b * 1024 + t * 4;
    int v[4];
    #pragma unroll
    for (int j = 0; j < 4; j++) {
        int idx = base + j;
        v[j] = (idx < Nn) ? g_counts[idx] : 0;
    }
    int s0 = v[0], s1 = s0 + v[1], s2 = s1 + v[2], s3 = s2 + v[3];
    int tot = s3;
    int xv = tot;
    #pragma unroll
    for (int o = 1; o < 32; o <<= 1) {
        int y = __shfl_up_sync(0xffffffffu, xv, o);
        if (lane >= o) xv += y;
    }
    if (lane == 31) warpSums[wid] = xv;
    __syncthreads();
    if (t == 0) {
        int acc = 0;
        for (int i = 0; i < 8; i++) { int tmp = warpSums[i]; warpSums[i] = acc; acc += tmp; }
    }
    __syncthreads();
    int off = chunkOff + warpSums[wid] + (xv - tot);
    int pre[4] = {0, s0, s1, s2};
    #pragma unroll
    for (int j = 0; j < 4; j++) {
        int idx = base + j;
        if (idx < Nn) g_rowptr[idx] = off + pre[j];
    }
}

__global__ void fill_csr(const void* ei, int E) {
    for (int i = blockIdx.x * blockDim.x + threadIdx.x; i < E;
         i += gridDim.x * blockDim.x) {
        int src = ld_idx(ei, i);
        int dst = ld_idx(ei, (long long)E + i);
        float coef = g_dis[src] * g_dis[dst];
        int pos = g_rowptr[dst] + atomicAdd(&g_fill[dst], 1);
        g_ecsr[pos] = make_int2(src, __float_as_int(coef));
    }
}

// ---- TF32 tensor-core GEMM, B pre-split, A register-prefetch, fp16 out -----
__device__ __forceinline__ void mma8(float* d, const unsigned* a, const unsigned* b) {
    asm volatile(
        "mma.sync.aligned.m16n8k8.row.col.f32.tf32.tf32.f32 "
        "{%0,%1,%2,%3}, {%4,%5,%6,%7}, {%8,%9}, {%0,%1,%2,%3};"
        : "+f"(d[0]), "+f"(d[1]), "+f"(d[2]), "+f"(d[3])
        : "r"(a[0]), "r"(a[1]), "r"(a[2]), "r"(a[3]), "r"(b[0]), "r"(b[1]));
}

template <int BN, bool HB>
__device__ __forceinline__ void gemm_tf32_body(const float* __restrict__ Ag,
                                               const unsigned* __restrict__ Bhi,
                                               const unsigned* __restrict__ Blo,
                                               __half* __restrict__ Cg, int M,
                                               int blk) {
    constexpr int WN = (BN == 128) ? 4 : 2;
    constexpr int WM = 8 / WN;
    constexpr int MI = (128 / WM) / 16;
    constexpr int NI = 4;
    constexpr int SA = 20;
    constexpr int SB = BN + 8;
    constexpr int NB = BN / 64;

    __shared__ unsigned sAhi[128 * SA], sAlo[128 * SA];
    __shared__ unsigned sBhi[16 * SB],  sBlo[16 * SB];

    int tid = threadIdx.x, lane = tid & 31, wid = tid >> 5;
    int wm = wid % WM, wn = wid / WM;
    int row0 = blk * 128;

    const float4* A4 = (const float4*)Ag;
    int rA0 = tid >> 2,          cA0 = tid & 3;
    int rA1 = (tid + 256) >> 2,  cA1 = (tid + 256) & 3;
    bool vA0 = (row0 + rA0) < M, vA1 = (row0 + rA1) < M;
    const float4 z4 = make_float4(0.f, 0.f, 0.f, 0.f);
    float4 pa0 = vA0 ? A4[(size_t)(row0 + rA0) * 32 + cA0] : z4;
    float4 pa1 = vA1 ? A4[(size_t)(row0 + rA1) * 32 + cA1] : z4;

    float acc[MI][NI][4];
    #pragma unroll
    for (int mi = 0; mi < MI; mi++)
        #pragma unroll
        for (int ni = 0; ni < NI; ni++)
            #pragma unroll
            for (int r = 0; r < 4; r++) acc[mi][ni][r] = 0.0f;

    for (int kk = 0; kk < 128; kk += 16) {
        __syncthreads();
        uint4 pbh[NB], pbl[NB];
        #pragma unroll
        for (int i = 0; i < NB; i++) {
            int idx = tid + i * 256;
            int rB = idx / (BN / 4), cB = idx % (BN / 4);
            pbh[i] = ((const uint4*)Bhi)[(size_t)(kk + rB) * (BN / 4) + cB];
            pbl[i] = ((const uint4*)Blo)[(size_t)(kk + rB) * (BN / 4) + cB];
        }
        {
            uint4 h, l;
            tf32_split(pa0.x, h.x, l.x); tf32_split(pa0.y, h.y, l.y);
            tf32_split(pa0.z, h.z, l.z); tf32_split(pa0.w, h.w, l.w);
            *(uint4*)&sAhi[rA0 * SA + cA0 * 4] = h;
            *(uint4*)&sAlo[rA0 * SA + cA0 * 4] = l;
            tf32_split(pa1.x, h.x, l.x); tf32_split(pa1.y, h.y, l.y);
            tf32_split(pa1.z, h.z, l.z); tf32_split(pa1.w, h.w, l.w);
            *(uint4*)&sAhi[rA1 * SA + cA1 * 4] = h;
            *(uint4*)&sAlo[rA1 * SA + cA1 * 4] = l;
        }
        #pragma unroll
        for (int i = 0; i < NB; i++) {
            int idx = tid + i * 256;
            int rB = idx / (BN / 4), cB = idx % (BN / 4);
            *(uint4*)&sBhi[rB * SB + cB * 4] = pbh[i];
            *(uint4*)&sBlo[rB * SB + cB * 4] = pbl[i];
        }
        __syncthreads();

        if (kk < 112) {
            int co = (kk >> 2) + 4;
            pa0 = vA0 ? A4[(size_t)(row0 + rA0) * 32 + co + cA0] : z4;
            pa1 = vA1 ? A4[(size_t)(row0 + rA1) * 32 + co + cA1] : z4;
        }

        #pragma unroll
        for (int ks = 0; ks < 2; ks++) {
            int kb = ks * 8;
            unsigned ahi[MI][4], alo[MI][4];
            #pragma unroll
            for (int mi = 0; mi < MI; mi++) {
                int r = wm * (MI * 16) + mi * 16 + (lane >> 2);
                int c = kb + (lane & 3);
                ahi[mi][0] = sAhi[r * SA + c];
                ahi[mi][1] = sAhi[(r + 8) * SA + c];
                ahi[mi][2] = sAhi[r * SA + c + 4];
                ahi[mi][3] = sAhi[(r + 8) * SA + c + 4];
                alo[mi][0] = sAlo[r * SA + c];
                alo[mi][1] = sAlo[(r + 8) * SA + c];
                alo[mi][2] = sAlo[r * SA + c + 4];
                alo[mi][3] = sAlo[(r + 8) * SA + c + 4];
            }
            unsigned bhi[NI][2], blo[NI][2];
            #pragma unroll
            for (int ni = 0; ni < NI; ni++) {
                int c = wn * 32 + ni * 8 + (lane >> 2);
                int r = kb + (lane & 3);
                bhi[ni][0] = sBhi[r * SB + c];
                bhi[ni][1] = sBhi[(r + 4) * SB + c];
                blo[ni][0] = sBlo[r * SB + c];
                blo[ni][1] = sBlo[(r + 4) * SB + c];
            }
            #pragma unroll
            for (int mi = 0; mi < MI; mi++)
                #pragma unroll
                for (int ni = 0; ni < NI; ni++) mma8(acc[mi][ni], ahi[mi], bhi[ni]);
            #pragma unroll
            for (int mi = 0; mi < MI; mi++)
                #pragma unroll
                for (int ni = 0; ni < NI; ni++) mma8(acc[mi][ni], ahi[mi], blo[ni]);
            #pragma unroll
            for (int mi = 0; mi < MI; mi++)
                #pragma unroll
                for (int ni = 0; ni < NI; ni++) mma8(acc[mi][ni], alo[mi], bhi[ni]);
        }
    }

    // epilogue: fp32 acc (+bias) -> fp16 store
    #pragma unroll
    for (int mi = 0; mi < MI; mi++) {
        int r = row0 + wm * (MI * 16) + mi * 16 + (lane >> 2);
        #pragma unroll
        for (int ni = 0; ni < NI; ni++) {
            int c = wn * 32 + ni * 8 + (lane & 3) * 2;
            float bx = 0.f, by = 0.f;
            if (HB) { bx = g_b12[c]; by = g_b12[c + 1]; }
            __half2 h0 = __floats2half2_rn(acc[mi][ni][0] + bx, acc[mi][ni][1] + by);
            __half2 h1v = __floats2half2_rn(acc[mi][ni][2] + bx, acc[mi][ni][3] + by);
            if (r < M)     *(__half2*)&Cg[(size_t)r * BN + c] = h0;
            if (r + 8 < M) *(__half2*)&Cg[(size_t)(r + 8) * BN + c] = h1v;
        }
    }
}

__global__ __launch_bounds__(256, 2) void gemm1_kernel(const float* __restrict__ x, int M) {
    gemm_tf32_body<128, true>(x, g_W12hi, g_W12lo, g_t1, M, blockIdx.x);
}

#define COUNT_BLOCKS 256
__global__ __launch_bounds__(256, 2) void gemm1_count_kernel(
    const float* __restrict__ x, const void* __restrict__ ei,
    int M, int E, int nGemmBlocks) {
    if ((int)blockIdx.x < nGemmBlocks) {
        gemm_tf32_body<128, true>(x, g_W12hi, g_W12lo, g_t1, M, blockIdx.x);
    } else {
        int b = blockIdx.x - nGemmBlocks;
        int stride = COUNT_BLOCKS * 256;
        for (int i = b * 256 + threadIdx.x; i < E; i += stride) {
            int dst = ld_idx(ei, (long long)E + i);
            atomicAdd(&g_counts[dst], 1);
        }
    }
}

__global__ __launch_bounds__(256, 2) void gemm2_kernel(int M) {
    gemm_tf32_body<64, false>(g_h1, g_W2hi, g_W2lo, g_t2, M, blockIdx.x);
}

// ---- conv1 gather: fp16 source, fp32 accumulate ----------------------------
__global__ void gather_conv1(const float* __restrict__ conv1_b,
                             const float* __restrict__ drop_u, int Nn) {
    int warp = (blockIdx.x * blockDim.x + threadIdx.x) >> 5;
    if (warp >= Nn) return;
    int lane = threadIdx.x & 31;
    int i = warp;
    const uint2* tb = (const uint2*)g_t1;   // 4 halves per lane; row = 32 uint2

    float4 acc = ((const float4*)conv1_b)[lane];
    float d = g_dis[i];
    float dsq = d * d;
    {
        uint2 raw = tb[(size_t)i * 32 + lane];
        float2 p0 = __half22float2(*(__half2*)&raw.x);
        float2 p1 = __half22float2(*(__half2*)&raw.y);
        acc.x += dsq * p0.x; acc.y += dsq * p0.y;
        acc.z += dsq * p1.x; acc.w += dsq * p1.y;
    }

    int s = g_rowptr[i], e = s + g_counts[i];
    #pragma unroll 4
    for (int j = s; j < e; j++) {
        int2 ed = __ldg(&g_ecsr[j]);
        float c = __int_as_float(ed.y);
        uint2 raw = __ldg(&tb[(size_t)ed.x * 32 + lane]);
        float2 p0 = __half22float2(*(__half2*)&raw.x);
        float2 p1 = __half22float2(*(__half2*)&raw.y);
        acc.x += c * p0.x; acc.y += c * p0.y;
        acc.z += c * p1.x; acc.w += c * p1.y;
    }

    float4 u = ((const float4*)drop_u)[(size_t)i * 32 + lane];
    float4 o;
    o.x = (u.x >= 0.5f) ? fmaxf(acc.x, 0.f) * 2.f : 0.f;
    o.y = (u.y >= 0.5f) ? fmaxf(acc.y, 0.f) * 2.f : 0.f;
    o.z = (u.z >= 0.5f) ? fmaxf(acc.z, 0.f) * 2.f : 0.f;
    o.w = (u.w >= 0.5f) ? fmaxf(acc.w, 0.f) * 2.f : 0.f;
    ((float4*)g_h1)[(size_t)i * 32 + lane] = o;
}

// ---- conv2 gather + mean-pool: fp16 source ---------------------------------
__global__ void gather_conv2_pool(const float* __restrict__ conv2_b,
                                  const void* __restrict__ batch, int Nn) {
    int warp = (blockIdx.x * blockDim.x + threadIdx.x) >> 5;
    if (warp >= Nn) return;
    int lane = threadIdx.x & 31;
    int i = warp;
    const unsigned* tb = (const unsigned*)g_t2;  // 2 halves per lane; row = 32 u32

    float2 acc = ((const float2*)conv2_b)[lane];
    float d = g_dis[i];
    float dsq = d * d;
    {
        unsigned raw = tb[(size_t)i * 32 + lane];
        float2 v = __half22float2(*(__half2*)&raw);
        acc.x += dsq * v.x; acc.y += dsq * v.y;
    }

    int s = g_rowptr[i], e = s + g_counts[i];
    #pragma unroll 4
    for (int j = s; j < e; j++) {
        int2 ed = __ldg(&g_ecsr[j]);
        float c = __int_as_float(ed.y);
        unsigned raw = __ldg(&tb[(size_t)ed.x * 32 + lane]);
        float2 w = __half22float2(*(__half2*)&raw);
        acc.x += c * w.x; acc.y += c * w.y;
    }

    int g = ld_idx(batch, i);
    atomicAdd(&g_pooled[g * HID2 + lane * 2], acc.x);
    atomicAdd(&g_pooled[g * HID2 + lane * 2 + 1], acc.y);
    if (lane == 0) atomicAdd(&g_gcnt[g], 1.0f);
}

__global__ void final_lin(const float* __restrict__ lin2_w,
                          const float* __restrict__ lin2_b,
                          float* __restrict__ out) {
    int g = blockIdx.x;
    int c = threadIdx.x;
    if (c >= NCLS) return;
    float inv = 1.0f / fmaxf(g_gcnt[g], 1.0f);
    float s = lin2_b[c];
    #pragma unroll
    for (int dd = 0; dd < HID2; dd++)
        s += g_pooled[g * HID2 + dd] * inv * lin2_w[dd * NCLS + c];
    out[g * NCLS + c] = s;
}

// ---- lazy stream/event creation --------------------------------------------
static int          g_streamState = 0;
static cudaStream_t g_s1;
static cudaEvent_t  g_ev0, g_ev1;

// ---------------------------------------------------------------------------
extern "C" void kernel_launch(void* const* d_in, const int* in_sizes, int n_in,
                              void* d_out, int out_size) {
    const float* x     = (const float*)d_in[0];
    const void*  ei    = d_in[1];
    const void*  batch = d_in[2];
    int idx = 3;
    if (n_in >= 13 && in_sizes[3] == 1) idx = 4;
    const float* drop_u  = (const float*)d_in[idx++];
    const float* lin1_w  = (const float*)d_in[idx++];
    const float* lin1_b  = (const float*)d_in[idx++];
    const float* conv1_w = (const float*)d_in[idx++];
    const float* conv1_b = (const float*)d_in[idx++];
    const float* conv2_w = (const float*)d_in[idx++];
    const float* conv2_b = (const float*)d_in[idx++];
    const float* lin2_w  = (const float*)d_in[idx++];
    const float* lin2_b  = (const float*)d_in[idx++];
    float* out = (float*)d_out;

    int Nn = in_sizes[0] / 128;
    int E  = in_sizes[1] / 2;
    if (Nn > 100000) Nn = 100000;
    if (E > E_CAP) E = E_CAP;
    int nb = (Nn + 1023) / 1024;
    int gb1 = (Nn + 127) / 128;

    if (g_streamState == 0) {
        bool ok =
            cudaStreamCreateWithFlags(&g_s1, cudaStreamNonBlocking) == cudaSuccess &&
            cudaEventCreateWithFlags(&g_ev0, cudaEventDisableTiming) == cudaSuccess &&
            cudaEventCreateWithFlags(&g_ev1, cudaEventDisableTiming) == cudaSuccess;
        g_streamState = ok ? 1 : -1;
    }
    bool fork = (g_streamState == 1);
    cudaStream_t s0 = 0;

    if (fork) {
        zero_buffers<<<(Nn + 255) / 256, 256, 0, s0>>>(Nn);
        probe_dtype<<<1, 1, 0, s0>>>((const long long*)ei);
        cudaEventRecord(g_ev0, s0);
        fuse_w<<<256, 128, 0, s0>>>(lin1_w, lin1_b, conv1_w, conv2_w);
        gemm1_kernel<<<gb1, 256, 0, s0>>>(x, Nn);

        cudaStreamWaitEvent(g_s1, g_ev0, 0);
        count_dst<<<1024, 256, 0, g_s1>>>(ei, E);
        dis_chunksums<<<nb, 256, 0, g_s1>>>(Nn);
        scan_chunks<<<nb, 256, 0, g_s1>>>(Nn);
        fill_csr<<<2048, 256, 0, g_s1>>>(ei, E);
        cudaEventRecord(g_ev1, g_s1);
        cudaStreamWaitEvent(s0, g_ev1, 0);
    } else {
        zero_buffers<<<(Nn + 255) / 256, 256, 0, s0>>>(Nn);
        probe_dtype<<<1, 1, 0, s0>>>((const long long*)ei);
        fuse_w<<<256, 128, 0, s0>>>(lin1_w, lin1_b, conv1_w, conv2_w);
        gemm1_count_kernel<<<gb1 + COUNT_BLOCKS, 256, 0, s0>>>(x, ei, Nn, E, gb1);
        dis_chunksums<<<nb, 256, 0, s0>>>(Nn);
        scan_chunks<<<nb, 256, 0, s0>>>(Nn);
        fill_csr<<<2048, 256, 0, s0>>>(ei, E);
    }

    gather_conv1<<<(Nn * 32 + 255) / 256, 256, 0, s0>>>(conv1_b, drop_u, Nn);
    gemm2_kernel<<<(Nn + 127) / 128, 256, 0, s0>>>(Nn);
    gather_conv2_pool<<<(Nn * 32 + 255) / 256, 256, 0, s0>>>(conv2_b, batch, Nn);
    final_lin<<<NGRAPH, 32, 0, s0>>>(lin2_w, lin2_b, out);
}

// round 16
// speedup vs baseline: 2.0607x; 1.5005x over previous
#include <cuda_runtime.h>
#include <cuda_fp16.h>

// ---------------------------------------------------------------------------
// GCN forward on GB300.  Round 15 (R13 with the MI=2 tiling bug fixed: MI=4).
//  - GEMM2 eliminated algebraically: mean-pool commutes with the conv2 linear
//    and the final linear -> aggregate h1 (fp16) directly, pool to
//    poolz[128x128], finish with 128x128x10 contraction vs W2L = conv2w@lin2w.
//  - h1 stored fp16; pooling via per-block smem reduction (batch sorted).
//  - Keeps: stream fork (CSR || GEMM1), tf32 3-term GEMM1 with A-prefetch.
// ---------------------------------------------------------------------------

#define NN_CAP 100352
#define E_CAP  1600000
#define NGRAPH 128
#define HID    128
#define NCLS   10

__device__ int      g_is64;
__device__ int      g_counts[NN_CAP];
__device__ int      g_rowptr[NN_CAP];
__device__ int      g_fill[NN_CAP];
__device__ int      g_chunkSum[256];
__device__ float    g_dis[NN_CAP];
__device__ int2     g_ecsr[E_CAP];
__device__ unsigned g_W12hi[128*128], g_W12lo[128*128];
__device__ float    g_b12[128];
__device__ float    g_W2L[128*NCLS];      // conv2_w @ lin2_w
__device__ float    g_bias2L[NCLS];       // conv2_b @ lin2_w + lin2_b
__device__ __half   g_t1[100000*128];     // fp16 gather source (conv1)
__device__ __half   g_h1[100000*128];     // fp16 gather source (conv2)
__device__ float    g_poolz[NGRAPH*HID];  // pooled aggregated h1
__device__ float    g_gcnt[NGRAPH];

// ---- index loading (int64 vs int32 decided at runtime) ---------------------
__device__ __forceinline__ int ld_idx(const void* p, long long i) {
    if (g_is64) return (int)((const long long*)p)[i];
    return ((const int*)p)[i];
}

__global__ void probe_dtype(const long long* ei) {
    if (blockIdx.x == 0 && threadIdx.x == 0) {
        int ok64 = 1;
        for (int i = 0; i < 128; i++) {
            long long v = ei[i];
            if (v < 0 || v >= 200000) { ok64 = 0; break; }
        }
        g_is64 = ok64;
    }
}

__global__ void zero_buffers(int Nn) {
    int i = blockIdx.x * blockDim.x + threadIdx.x;
    if (i < Nn) { g_counts[i] = 0; g_fill[i] = 0; }
    if (i < NGRAPH * HID) g_poolz[i] = 0.0f;
    if (i < NGRAPH) g_gcnt[i] = 0.0f;
}

__global__ void count_dst(const void* ei, int E) {
    for (int i = blockIdx.x * blockDim.x + threadIdx.x; i < E;
         i += gridDim.x * blockDim.x) {
        int dst = ld_idx(ei, (long long)E + i);
        atomicAdd(&g_counts[dst], 1);
    }
}

// ---- tf32 split helper -----------------------------------------------------
__device__ __forceinline__ void tf32_split(float v, unsigned& hi, unsigned& lo) {
    asm("cvt.rna.tf32.f32 %0, %1;" : "=r"(hi) : "f"(v));
    float r = v - __uint_as_float(hi);
    asm("cvt.rna.tf32.f32 %0, %1;" : "=r"(lo) : "f"(r));
}

// ---- weight prep: W12=lin1@conv1 (split), W2L=conv2@lin2, folded biases ----
__global__ void fuse_w(const float* __restrict__ lin1_w,
                       const float* __restrict__ lin1_b,
                       const float* __restrict__ conv1_w,
                       const float* __restrict__ conv2_w,
                       const float* __restrict__ conv2_b,
                       const float* __restrict__ lin2_w,
                       const float* __restrict__ lin2_b) {
    int i = blockIdx.x, j = threadIdx.x;
    if (i < 128) {
        float s = 0.0f;
        #pragma unroll 8
        for (int k = 0; k < 128; k++) s += lin1_w[i * 128 + k] * conv1_w[k * 128 + j];
        unsigned hi, lo;
        tf32_split(s, hi, lo);
        g_W12hi[i * 128 + j] = hi;
        g_W12lo[i * 128 + j] = lo;
        if (i == 0) {
            float sb = 0.0f;
            #pragma unroll 8
            for (int k = 0; k < 128; k++) sb += lin1_b[k] * conv1_w[k * 128 + j];
            g_b12[j] = sb;
        }
    } else {
        int r = j;
        float acc[NCLS];
        #pragma unroll
        for (int c = 0; c < NCLS; c++) acc[c] = 0.0f;
        for (int k = 0; k < 64; k++) {
            float w = conv2_w[r * 64 + k];
            #pragma unroll
            for (int c = 0; c < NCLS; c++) acc[c] += w * lin2_w[k * NCLS + c];
        }
        #pragma unroll
        for (int c = 0; c < NCLS; c++) g_W2L[r * NCLS + c] = acc[c];
        if (j < NCLS) {
            float sb = lin2_b[j];
            for (int k = 0; k < 64; k++) sb += conv2_b[k] * lin2_w[k * NCLS + j];
            g_bias2L[j] = sb;
        }
    }
}

// ---- fused compute_dis + chunk_sums ---------------------------------------
__global__ void dis_chunksums(int Nn) {
    __shared__ int sm[256];
    int b = blockIdx.x, t = threadIdx.x;
    int s = 0;
    #pragma unroll
    for (int j = 0; j < 4; j++) {
        int idx = b * 1024 + t + j * 256;
        if (idx < Nn) {
            int c = g_counts[idx];
            s += c;
            g_dis[idx] = rsqrtf((float)(c + 1));
        }
    }
    sm[t] = s; __syncthreads();
    for (int o = 128; o > 0; o >>= 1) {
        if (t < o) sm[t] += sm[t + o];
        __syncthreads();
    }
    if (t == 0) g_chunkSum[b] = sm[0];
}

// ---- scan_chunks with inline top-scan --------------------------------------
__global__ void scan_chunks(int Nn) {
    __shared__ int warpSums[8];
    __shared__ int smTop[256];
    int b = blockIdx.x, t = threadIdx.x;
    int lane = t & 31, wid = t >> 5;

    smTop[t] = (t < b) ? g_chunkSum[t] : 0;
    __syncthreads();
    for (int o = 128; o > 0; o >>= 1) {
        if (t < o) smTop[t] += smTop[t + o];
        __syncthreads();
    }
    int chunkOff = smTop[0];
    __syncthreads();

    int base = b * 1024 + t * 4;
    int v[4];
    #pragma unroll
    for (int j = 0; j < 4; j++) {
        int idx = base + j;
        v[j] = (idx < Nn) ? g_counts[idx] : 0;
    }
    int s0 = v[0], s1 = s0 + v[1], s2 = s1 + v[2], s3 = s2 + v[3];
    int tot = s3;
    int xv = tot;
    #pragma unroll
    for (int o = 1; o < 32; o <<= 1) {
        int y = __shfl_up_sync(0xffffffffu, xv, o);
        if (lane >= o) xv += y;
    }
    if (lane == 31) warpSums[wid] = xv;
    __syncthreads();
    if (t == 0) {
        int acc = 0;
        for (int i = 0; i < 8; i++) { int tmp = warpSums[i]; warpSums[i] = acc; acc += tmp; }
    }
    __syncthreads();
    int off = chunkOff + warpSums[wid] + (xv - tot);
    int pre[4] = {0, s0, s1, s2};
    #pragma unroll
    for (int j = 0; j < 4; j++) {
        int idx = base + j;
        if (idx < Nn) g_rowptr[idx] = off + pre[j];
    }
}

__global__ void fill_csr(const void* ei, int E) {
    for (int i = blockIdx.x * blockDim.x + threadIdx.x; i < E;
         i += gridDim.x * blockDim.x) {
        int src = ld_idx(ei, i);
        int dst = ld_idx(ei, (long long)E + i);
        float coef = g_dis[src] * g_dis[dst];
        int pos = g_rowptr[dst] + atomicAdd(&g_fill[dst], 1);
        g_ecsr[pos] = make_int2(src, __float_as_int(coef));
    }
}

// ---- TF32 tensor-core GEMM1, B pre-split, A register-prefetch, fp16 out ----
__device__ __forceinline__ void mma8(float* d, const unsigned* a, const unsigned* b) {
    asm volatile(
        "mma.sync.aligned.m16n8k8.row.col.f32.tf32.tf32.f32 "
        "{%0,%1,%2,%3}, {%4,%5,%6,%7}, {%8,%9}, {%0,%1,%2,%3};"
        : "+f"(d[0]), "+f"(d[1]), "+f"(d[2]), "+f"(d[3])
        : "r"(a[0]), "r"(a[1]), "r"(a[2]), "r"(a[3]), "r"(b[0]), "r"(b[1]));
}

__device__ __forceinline__ void gemm1_body(const float* __restrict__ Ag,
                                           int M, int blk) {
    constexpr int BN = 128;
    constexpr int MI = 4;          // WM=2 -> each warp covers 64 rows (4 x m16)
    constexpr int NI = 4;
    constexpr int SA = 20;
    constexpr int SB = BN + 8;

    __shared__ unsigned sAhi[128 * SA], sAlo[128 * SA];
    __shared__ unsigned sBhi[16 * SB],  sBlo[16 * SB];

    int tid = threadIdx.x, lane = tid & 31, wid = tid >> 5;
    int wm = wid % 2, wn = wid / 2;
    int row0 = blk * 128;

    const float4* A4 = (const float4*)Ag;
    int rA0 = tid >> 2,          cA0 = tid & 3;
    int rA1 = (tid + 256) >> 2,  cA1 = (tid + 256) & 3;
    bool vA0 = (row0 + rA0) < M, vA1 = (row0 + rA1) < M;
    const float4 z4 = make_float4(0.f, 0.f, 0.f, 0.f);
    float4 pa0 = vA0 ? A4[(size_t)(row0 + rA0) * 32 + cA0] : z4;
    float4 pa1 = vA1 ? A4[(size_t)(row0 + rA1) * 32 + cA1] : z4;

    float acc[MI][NI][4];
    #pragma unroll
    for (int mi = 0; mi < MI; mi++)
        #pragma unroll
        for (int ni = 0; ni < NI; ni++)
            #pragma unroll
            for (int r = 0; r < 4; r++) acc[mi][ni][r] = 0.0f;

    for (int kk = 0; kk < 128; kk += 16) {
        __syncthreads();
        uint4 pbh[2], pbl[2];
        #pragma unroll
        for (int i = 0; i < 2; i++) {
            int idx = tid + i * 256;
            int rB = idx >> 5, cB = idx & 31;
            pbh[i] = ((const uint4*)g_W12hi)[(size_t)(kk + rB) * 32 + cB];
            pbl[i] = ((const uint4*)g_W12lo)[(size_t)(kk + rB) * 32 + cB];
        }
        {
            uint4 h, l;
            tf32_split(pa0.x, h.x, l.x); tf32_split(pa0.y, h.y, l.y);
            tf32_split(pa0.z, h.z, l.z); tf32_split(pa0.w, h.w, l.w);
            *(uint4*)&sAhi[rA0 * SA + cA0 * 4] = h;
            *(uint4*)&sAlo[rA0 * SA + cA0 * 4] = l;
            tf32_split(pa1.x, h.x, l.x); tf32_split(pa1.y, h.y, l.y);
            tf32_split(pa1.z, h.z, l.z); tf32_split(pa1.w, h.w, l.w);
            *(uint4*)&sAhi[rA1 * SA + cA1 * 4] = h;
            *(uint4*)&sAlo[rA1 * SA + cA1 * 4] = l;
        }
        #pragma unroll
        for (int i = 0; i < 2; i++) {
            int idx = tid + i * 256;
            int rB = idx >> 5, cB = idx & 31;
            *(uint4*)&sBhi[rB * SB + cB * 4] = pbh[i];
            *(uint4*)&sBlo[rB * SB + cB * 4] = pbl[i];
        }
        __syncthreads();

        if (kk < 112) {
            int co = (kk >> 2) + 4;
            pa0 = vA0 ? A4[(size_t)(row0 + rA0) * 32 + co + cA0] : z4;
            pa1 = vA1 ? A4[(size_t)(row0 + rA1) * 32 + co + cA1] : z4;
        }

        #pragma unroll
        for (int ks = 0; ks < 2; ks++) {
            int kb = ks * 8;
            unsigned ahi[MI][4], alo[MI][4];
            #pragma unroll
            for (int mi = 0; mi < MI; mi++) {
                int r = wm * 64 + mi * 16 + (lane >> 2);
                int c = kb + (lane & 3);
                ahi[mi][0] = sAhi[r * SA + c];
                ahi[mi][1] = sAhi[(r + 8) * SA + c];
                ahi[mi][2] = sAhi[r * SA + c + 4];
                ahi[mi][3] = sAhi[(r + 8) * SA + c + 4];
                alo[mi][0] = sAlo[r * SA + c];
                alo[mi][1] = sAlo[(r + 8) * SA + c];
                alo[mi][2] = sAlo[r * SA + c + 4];
                alo[mi][3] = sAlo[(r + 8) * SA + c + 4];
            }
            unsigned bhi[NI][2], blo[NI][2];
            #pragma unroll
            for (int ni = 0; ni < NI; ni++) {
                int c = wn * 32 + ni * 8 + (lane >> 2);
                int r = kb + (lane & 3);
                bhi[ni][0] = sBhi[r * SB + c];
                bhi[ni][1] = sBhi[(r + 4) * SB + c];
                blo[ni][0] = sBlo[r * SB + c];
                blo[ni][1] = sBlo[(r + 4) * SB + c];
            }
            #pragma unroll
            for (int mi = 0; mi < MI; mi++)
                #pragma unroll
                for (int ni = 0; ni < NI; ni++) mma8(acc[mi][ni], ahi[mi], bhi[ni]);
            #pragma unroll
            for (int mi = 0; mi < MI; mi++)
                #pragma unroll
                for (int ni = 0; ni < NI; ni++) mma8(acc[mi][ni], ahi[mi], blo[ni]);
            #pragma unroll
            for (int mi = 0; mi < MI; mi++)
                #pragma unroll
                for (int ni = 0; ni < NI; ni++) mma8(acc[mi][ni], alo[mi], bhi[ni]);
        }
    }

    #pragma unroll
    for (int mi = 0; mi < MI; mi++) {
        int r = row0 + wm * 64 + mi * 16 + (lane >> 2);
        #pragma unroll
        for (int ni = 0; ni < NI; ni++) {
            int c = wn * 32 + ni * 8 + (lane & 3) * 2;
            float bx = g_b12[c], by = g_b12[c + 1];
            __half2 h0 = __floats2half2_rn(acc[mi][ni][0] + bx, acc[mi][ni][1] + by);
            __half2 h1v = __floats2half2_rn(acc[mi][ni][2] + bx, acc[mi][ni][3] + by);
            if (r < M)     *(__half2*)&g_t1[(size_t)r * 128 + c] = h0;
            if (r + 8 < M) *(__half2*)&g_t1[(size_t)(r + 8) * 128 + c] = h1v;
        }
    }
}

__global__ __launch_bounds__(256, 2) void gemm1_kernel(const float* __restrict__ x, int M) {
    gemm1_body(x, M, blockIdx.x);
}

#define COUNT_BLOCKS 256
__global__ __launch_bounds__(256, 2) void gemm1_count_kernel(
    const float* __restrict__ x, const void* __restrict__ ei,
    int M, int E, int nGemmBlocks) {
    if ((int)blockIdx.x < nGemmBlocks) {
        gemm1_body(x, M, blockIdx.x);
    } else {
        int b = blockIdx.x - nGemmBlocks;
        int stride = COUNT_BLOCKS * 256;
        for (int i = b * 256 + threadIdx.x; i < E; i += stride) {
            int dst = ld_idx(ei, (long long)E + i);
            atomicAdd(&g_counts[dst], 1);
        }
    }
}

// ---- conv1 gather: fp16 in, fp16 out (dropout+relu) ------------------------
__global__ void gather_conv1(const float* __restrict__ conv1_b,
                             const float* __restrict__ drop_u, int Nn) {
    int warp = (blockIdx.x * blockDim.x + threadIdx.x) >> 5;
    if (warp >= Nn) return;
    int lane = threadIdx.x & 31;
    int i = warp;
    const uint2* tb = (const uint2*)g_t1;

    float4 acc = ((const float4*)conv1_b)[lane];
    float d = g_dis[i];
    float dsq = d * d;
    {
        uint2 raw = tb[(size_t)i * 32 + lane];
        float2 p0 = __half22float2(*(__half2*)&raw.x);
        float2 p1 = __half22float2(*(__half2*)&raw.y);
        acc.x += dsq * p0.x; acc.y += dsq * p0.y;
        acc.z += dsq * p1.x; acc.w += dsq * p1.y;
    }

    int s = g_rowptr[i], e = s + g_counts[i];
    #pragma unroll 4
    for (int j = s; j < e; j++) {
        int2 ed = __ldg(&g_ecsr[j]);
        float c = __int_as_float(ed.y);
        uint2 raw = __ldg(&tb[(size_t)ed.x * 32 + lane]);
        float2 p0 = __half22float2(*(__half2*)&raw.x);
        float2 p1 = __half22float2(*(__half2*)&raw.y);
        acc.x += c * p0.x; acc.y += c * p0.y;
        acc.z += c * p1.x; acc.w += c * p1.y;
    }

    float4 u = ((const float4*)drop_u)[(size_t)i * 32 + lane];
    float ox = (u.x >= 0.5f) ? fmaxf(acc.x, 0.f) * 2.f : 0.f;
    float oy = (u.y >= 0.5f) ? fmaxf(acc.y, 0.f) * 2.f : 0.f;
    float oz = (u.z >= 0.5f) ? fmaxf(acc.z, 0.f) * 2.f : 0.f;
    float ow = (u.w >= 0.5f) ? fmaxf(acc.w, 0.f) * 2.f : 0.f;
    __half2 h0 = __floats2half2_rn(ox, oy);
    __half2 h1v = __floats2half2_rn(oz, ow);
    uint2 packed;
    packed.x = *(unsigned*)&h0;
    packed.y = *(unsigned*)&h1v;
    ((uint2*)g_h1)[(size_t)i * 32 + lane] = packed;
}

// ---- conv2 aggregate + mean-pool (no GEMM; W2 applied post-pool) -----------
__global__ void gather_pool2(const void* __restrict__ batch, int Nn) {
    __shared__ float zbuf[128][9];   // [dim][warp], padded
    __shared__ int   gids[8];
    int t = threadIdx.x;
    int lane = t & 31, w = t >> 5;
    int node = blockIdx.x * 8 + w;
    bool valid = node < Nn;

    float4 z = make_float4(0.f, 0.f, 0.f, 0.f);
    int g = -1;
    if (valid) {
        const uint2* tb = (const uint2*)g_h1;
        float d = g_dis[node];
        float dsq = d * d;
        {
            uint2 raw = tb[(size_t)node * 32 + lane];
            float2 p0 = __half22float2(*(__half2*)&raw.x);
            float2 p1 = __half22float2(*(__half2*)&raw.y);
            z.x += dsq * p0.x; z.y += dsq * p0.y;
            z.z += dsq * p1.x; z.w += dsq * p1.y;
        }
        int s = g_rowptr[node], e = s + g_counts[node];
        #pragma unroll 4
        for (int j = s; j < e; j++) {
            int2 ed = __ldg(&g_ecsr[j]);
            float c = __int_as_float(ed.y);
            uint2 raw = __ldg(&tb[(size_t)ed.x * 32 + lane]);
            float2 p0 = __half22float2(*(__half2*)&raw.x);
            float2 p1 = __half22float2(*(__half2*)&raw.y);
            z.x += c * p0.x; z.y += c * p0.y;
            z.z += c * p1.x; z.w += c * p1.y;
        }
        g = ld_idx(batch, node);
    }

    zbuf[lane * 4 + 0][w] = z.x;
    zbuf[lane * 4 + 1][w] = z.y;
    zbuf[lane * 4 + 2][w] = z.z;
    zbuf[lane * 4 + 3][w] = z.w;
    if (lane == 0) gids[w] = valid ? g : -1;
    __syncthreads();

    bool uniform = (gids[0] >= 0);
    #pragma unroll
    for (int i = 1; i < 8; i++) uniform = uniform && (gids[i] == gids[0]);

    if (uniform) {
        if (t < 128) {
            float s = 0.f;
            #pragma unroll
            for (int i = 0; i < 8; i++) s += zbuf[t][i];
            atomicAdd(&g_poolz[gids[0] * HID + t], s);
        }
        if (t == 0) atomicAdd(&g_gcnt[gids[0]], 8.0f);
    } else if (valid) {
        atomicAdd(&g_poolz[g * HID + lane * 4 + 0], z.x);
        atomicAdd(&g_poolz[g * HID + lane * 4 + 1], z.y);
        atomicAdd(&g_poolz[g * HID + lane * 4 + 2], z.z);
        atomicAdd(&g_poolz[g * HID + lane * 4 + 3], z.w);
        if (lane == 0) atomicAdd(&g_gcnt[g], 1.0f);
    }
}

// ---- final: out[g,c] = inv * poolz[g] . W2L[:,c] + bias2L[c] ---------------
__global__ void final_out(float* __restrict__ out) {
    int g = blockIdx.x;
    int c = threadIdx.x;
    if (c >= NCLS) return;
    float inv = 1.0f / fmaxf(g_gcnt[g], 1.0f);
    float s = 0.0f;
    #pragma unroll 8
    for (int d = 0; d < HID; d++)
        s += g_poolz[g * HID + d] * g_W2L[d * NCLS + c];
    out[g * NCLS + c] = s * inv + g_bias2L[c];
}

// ---- lazy stream/event creation --------------------------------------------
static int          g_streamState = 0;
static cudaStream_t g_s1;
static cudaEvent_t  g_ev0, g_ev1;

// ---------------------------------------------------------------------------
extern "C" void kernel_launch(void* const* d_in, const int* in_sizes, int n_in,
                              void* d_out, int out_size) {
    const float* x     = (const float*)d_in[0];
    const void*  ei    = d_in[1];
    const void*  batch = d_in[2];
    int idx = 3;
    if (n_in >= 13 && in_sizes[3] == 1) idx = 4;
    const float* drop_u  = (const float*)d_in[idx++];
    const float* lin1_w  = (const float*)d_in[idx++];
    const float* lin1_b  = (const float*)d_in[idx++];
    const float* conv1_w = (const float*)d_in[idx++];
    const float* conv1_b = (const float*)d_in[idx++];
    const float* conv2_w = (const float*)d_in[idx++];
    const float* conv2_b = (const float*)d_in[idx++];
    const float* lin2_w  = (const float*)d_in[idx++];
    const float* lin2_b  = (const float*)d_in[idx++];
    float* out = (float*)d_out;

    int Nn = in_sizes[0] / 128;
    int E  = in_sizes[1] / 2;
    if (Nn > 100000) Nn = 100000;
    if (E > E_CAP) E = E_CAP;
    int nb = (Nn + 1023) / 1024;
    int gb1 = (Nn + 127) / 128;

    if (g_streamState == 0) {
        bool ok =
            cudaStreamCreateWithFlags(&g_s1, cudaStreamNonBlocking) == cudaSuccess &&
            cudaEventCreateWithFlags(&g_ev0, cudaEventDisableTiming) == cudaSuccess &&
            cudaEventCreateWithFlags(&g_ev1, cudaEventDisableTiming) == cudaSuccess;
        g_streamState = ok ? 1 : -1;
    }
    bool fork = (g_streamState == 1);
    cudaStream_t s0 = 0;

    if (fork) {
        zero_buffers<<<(Nn + 255) / 256, 256, 0, s0>>>(Nn);
        probe_dtype<<<1, 1, 0, s0>>>((const long long*)ei);
        cudaEventRecord(g_ev0, s0);
        fuse_w<<<129, 128, 0, s0>>>(lin1_w, lin1_b, conv1_w, conv2_w,
                                    conv2_b, lin2_w, lin2_b);
        gemm1_kernel<<<gb1, 256, 0, s0>>>(x, Nn);   // launch #4 -> ncu window

        cudaStreamWaitEvent(g_s1, g_ev0, 0);
        count_dst<<<1024, 256, 0, g_s1>>>(ei, E);
        dis_chunksums<<<nb, 256, 0, g_s1>>>(Nn);
        scan_chunks<<<nb, 256, 0, g_s1>>>(Nn);
        fill_csr<<<2048, 256, 0, g_s1>>>(ei, E);
        cudaEventRecord(g_ev1, g_s1);
        cudaStreamWaitEvent(s0, g_ev1, 0);
    } else {
        zero_buffers<<<(Nn + 255) / 256, 256, 0, s0>>>(Nn);
        probe_dtype<<<1, 1, 0, s0>>>((const long long*)ei);
        fuse_w<<<129, 128, 0, s0>>>(lin1_w, lin1_b, conv1_w, conv2_w,
                                    conv2_b, lin2_w, lin2_b);
        gemm1_count_kernel<<<gb1 + COUNT_BLOCKS, 256, 0, s0>>>(x, ei, Nn, E, gb1);
        dis_chunksums<<<nb, 256, 0, s0>>>(Nn);
        scan_chunks<<<nb, 256, 0, s0>>>(Nn);
        fill_csr<<<2048, 256, 0, s0>>>(ei, E);
    }

    gather_conv1<<<(Nn * 32 + 255) / 256, 256, 0, s0>>>(conv1_b, drop_u, Nn);
    gather_pool2<<<(Nn + 7) / 8, 256, 0, s0>>>(batch, Nn);
    final_out<<<NGRAPH, 32, 0, s0>>>(out);
}